// round 1
// baseline (speedup 1.0000x reference)
#include <cuda_runtime.h>
#include <math.h>

#define NN    50000
#define EE    800000
#define INC   128
#define HEADS 4
#define HIDC  64
#define HC    256       // HEADS*HIDC
#define NCLS  200
#define GG    64
#define NEG   0.2f

// ---------------- scratch (static device globals; no allocation) -------------
__device__ float g_bufA[NN * HC];
__device__ float g_bufB[NN * HC];
__device__ float g_as[NN * HEADS];
__device__ float g_ad[NN * HEADS];
__device__ int   g_deg[NN];
__device__ int   g_rowptr[NN + 1];
__device__ int   g_wp[NN];
__device__ int   g_csr[EE];
__device__ float g_pool[GG * HIDC];
__device__ float g_cnt[GG];

__device__ __forceinline__ float leaky(float z) { return z > 0.f ? z : NEG * z; }

// ---------------- graph prep ------------------------------------------------
__global__ void zero_kernel() {
    int tid = blockIdx.x * blockDim.x + threadIdx.x;
    if (tid < NN) g_deg[tid] = 0;
    if (tid < GG * HIDC) g_pool[tid] = 0.f;
    if (tid < GG) g_cnt[tid] = 0.f;
}

__global__ void hist_kernel(const int* __restrict__ ei) {
    int e = blockIdx.x * blockDim.x + threadIdx.x;
    if (e < EE) atomicAdd(&g_deg[ei[EE + e]], 1);
}

__global__ void scan_kernel() {
    __shared__ int sh[1024];
    int t = threadIdx.x;
    const int CHK = (NN + 1023) / 1024;
    int base = t * CHK;
    int s = 0;
    for (int i = 0; i < CHK; i++) {
        int idx = base + i;
        if (idx < NN) s += g_deg[idx];
    }
    sh[t] = s;
    __syncthreads();
    for (int off = 1; off < 1024; off <<= 1) {
        int v = (t >= off) ? sh[t - off] : 0;
        __syncthreads();
        sh[t] += v;
        __syncthreads();
    }
    int run = sh[t] - s;   // exclusive prefix
    for (int i = 0; i < CHK; i++) {
        int idx = base + i;
        if (idx < NN) {
            g_rowptr[idx] = run;
            g_wp[idx] = run;
            run += g_deg[idx];
        }
    }
    if (t == 1023) g_rowptr[NN] = sh[1023];
}

__global__ void scatter_kernel(const int* __restrict__ ei) {
    int e = blockIdx.x * blockDim.x + threadIdx.x;
    if (e < EE) {
        int d = ei[EE + e];
        int p = atomicAdd(&g_wp[d], 1);
        g_csr[p] = ei[e];   // store src
    }
}

// ---------------- SGEMM: C[M,Nn] = A[M,K] @ B[K,Nn] --------------------------
template <int BM, int BN, int BK, int TM, int TN>
__global__ void sgemm_kernel(const float* __restrict__ A, const float* __restrict__ B,
                             float* __restrict__ C, int M, int K, int Nn) {
    __shared__ float As[BK][BM + 1];
    __shared__ float Bs[BK][BN];
    const int bm = blockIdx.x * BM, bn = blockIdx.y * BN;
    const int tid = threadIdx.x;
    const int tr = tid / (BN / TN), tc = tid % (BN / TN);
    float acc[TM][TN];
#pragma unroll
    for (int m = 0; m < TM; m++)
#pragma unroll
        for (int n = 0; n < TN; n++) acc[m][n] = 0.f;

    for (int k0 = 0; k0 < K; k0 += BK) {
#pragma unroll
        for (int i = 0; i < (BM * BK) / 256; i++) {
            int idx = i * 256 + tid;
            int r = idx / BK, c = idx % BK;
            int row = bm + r;
            As[c][r] = (row < M) ? A[row * K + k0 + c] : 0.f;
        }
#pragma unroll
        for (int i = 0; i < (BK * BN) / 256; i++) {
            int idx = i * 256 + tid;
            int r = idx / BN, c = idx % BN;
            Bs[r][c] = B[(k0 + r) * Nn + bn + c];
        }
        __syncthreads();
#pragma unroll
        for (int k = 0; k < BK; k++) {
            float rm[TM], rn[TN];
#pragma unroll
            for (int m = 0; m < TM; m++) rm[m] = As[k][tr * TM + m];
#pragma unroll
            for (int n = 0; n < TN; n++) rn[n] = Bs[k][tc * TN + n];
#pragma unroll
            for (int m = 0; m < TM; m++)
#pragma unroll
                for (int n = 0; n < TN; n++) acc[m][n] += rm[m] * rn[n];
        }
        __syncthreads();
    }
#pragma unroll
    for (int m = 0; m < TM; m++) {
        int row = bm + tr * TM + m;
        if (row < M) {
#pragma unroll
            for (int n = 0; n < TN; n++) C[row * Nn + bn + tc * TN + n] = acc[m][n];
        }
    }
}

// ---------------- per-node attention logits ----------------------------------
template <int H, int C>
__global__ void alpha_kernel(const float* __restrict__ h, const float* __restrict__ a_s,
                             const float* __restrict__ a_d) {
    int gw = (blockIdx.x * blockDim.x + threadIdx.x) >> 5;
    int lane = threadIdx.x & 31;
    if (gw >= NN) return;
    const int HCc = H * C, PER = HCc / 32;
    float ps[H], pd[H];
#pragma unroll
    for (int hh = 0; hh < H; hh++) { ps[hh] = 0.f; pd[hh] = 0.f; }
#pragma unroll
    for (int j = 0; j < PER; j++) {
        int c = lane + 32 * j;
        float v = h[gw * HCc + c];
        const int hh = (32 * j) / C;   // lane<32 so head is j-determined
        ps[hh] += v * a_s[c];
        pd[hh] += v * a_d[c];
    }
#pragma unroll
    for (int hh = 0; hh < H; hh++) {
        for (int o = 16; o > 0; o >>= 1) {
            ps[hh] += __shfl_xor_sync(0xffffffffu, ps[hh], o);
            pd[hh] += __shfl_xor_sync(0xffffffffu, pd[hh], o);
        }
    }
    if (lane == 0) {
#pragma unroll
        for (int hh = 0; hh < H; hh++) {
            g_as[gw * H + hh] = ps[hh];
            g_ad[gw * H + hh] = pd[hh];
        }
    }
}

// ---------------- gather-side GAT aggregation (warp per dst node) ------------
template <int H, int C>
__global__ void agg_kernel(const float* __restrict__ h, const float* __restrict__ bias,
                           float* __restrict__ out) {
    const int HCc = H * C, PER = HCc / 32;
    __shared__ float w_sh[8][32 * H];
    __shared__ int   s_sh[8][32];
    const int wid = threadIdx.x >> 5, lane = threadIdx.x & 31;
    const int n = (blockIdx.x * blockDim.x + threadIdx.x) >> 5;
    if (n >= NN) return;

    const int start = g_rowptr[n], end = g_rowptr[n + 1];
    float adv[H], asv[H];
#pragma unroll
    for (int hh = 0; hh < H; hh++) {
        adv[hh] = g_ad[n * H + hh];
        asv[hh] = g_as[n * H + hh];
    }
    // pass 1: max over edges (incl. self loop)
    float m[H];
#pragma unroll
    for (int hh = 0; hh < H; hh++) m[hh] = leaky(asv[hh] + adv[hh]);
    for (int i = start + lane; i < end; i += 32) {
        int s = g_csr[i];
#pragma unroll
        for (int hh = 0; hh < H; hh++)
            m[hh] = fmaxf(m[hh], leaky(g_as[s * H + hh] + adv[hh]));
    }
#pragma unroll
    for (int hh = 0; hh < H; hh++)
        for (int o = 16; o > 0; o >>= 1)
            m[hh] = fmaxf(m[hh], __shfl_xor_sync(0xffffffffu, m[hh], o));

    // pass 2: denom
    float den[H];
#pragma unroll
    for (int hh = 0; hh < H; hh++)
        den[hh] = (lane == 0) ? __expf(leaky(asv[hh] + adv[hh]) - m[hh]) : 0.f;
    for (int i = start + lane; i < end; i += 32) {
        int s = g_csr[i];
#pragma unroll
        for (int hh = 0; hh < H; hh++)
            den[hh] += __expf(leaky(g_as[s * H + hh] + adv[hh]) - m[hh]);
    }
    float inv[H];
#pragma unroll
    for (int hh = 0; hh < H; hh++) {
        for (int o = 16; o > 0; o >>= 1)
            den[hh] += __shfl_xor_sync(0xffffffffu, den[hh], o);
        inv[hh] = 1.f / (den[hh] + 1e-16f);
    }

    // pass 3: weighted gather (self edge first)
    float acc[PER];
    {
        float ws[H];
#pragma unroll
        for (int hh = 0; hh < H; hh++)
            ws[hh] = __expf(leaky(asv[hh] + adv[hh]) - m[hh]) * inv[hh];
#pragma unroll
        for (int j = 0; j < PER; j++) {
            int c = lane + 32 * j;
            acc[j] = h[n * HCc + c] * ws[(32 * j) / C];
        }
    }
    for (int base = start; base < end; base += 32) {
        int i = base + lane;
        if (i < end) {
            int s = g_csr[i];
            s_sh[wid][lane] = s;
#pragma unroll
            for (int hh = 0; hh < H; hh++)
                w_sh[wid][lane * H + hh] =
                    __expf(leaky(g_as[s * H + hh] + adv[hh]) - m[hh]) * inv[hh];
        }
        __syncwarp();
        int cnt = min(32, end - base);
        for (int k = 0; k < cnt; k++) {
            int s = s_sh[wid][k];
#pragma unroll
            for (int j = 0; j < PER; j++) {
                int c = lane + 32 * j;
                acc[j] += h[s * HCc + c] * w_sh[wid][k * H + (32 * j) / C];
            }
        }
        __syncwarp();
    }
    // epilogue: + bias, ELU
#pragma unroll
    for (int j = 0; j < PER; j++) {
        int c = lane + 32 * j;
        float v = acc[j] + bias[c];
        out[n * HCc + c] = v > 0.f ? v : (__expf(v) - 1.f);
    }
}

// ---------------- pooling + classifier ---------------------------------------
__global__ void pool_kernel(const float* __restrict__ h, const int* __restrict__ batch) {
    int tid = blockIdx.x * blockDim.x + threadIdx.x;
    if (tid >= NN * HIDC) return;
    int node = tid / HIDC, c = tid % HIDC;
    int g = batch[node];
    atomicAdd(&g_pool[g * HIDC + c], h[node * HIDC + c]);
    if (c == 0) atomicAdd(&g_cnt[g], 1.f);
}

__global__ void cls_kernel(const float* __restrict__ Wc, const float* __restrict__ bc,
                           float* __restrict__ out) {
    __shared__ float p[HIDC];
    int g = blockIdx.x;
    if (threadIdx.x < HIDC)
        p[threadIdx.x] = g_pool[g * HIDC + threadIdx.x] / fmaxf(g_cnt[g], 1.f);
    __syncthreads();
    for (int k = threadIdx.x; k < NCLS; k += blockDim.x) {
        float s = bc[k];
#pragma unroll
        for (int c = 0; c < HIDC; c++) s += p[c] * Wc[c * NCLS + k];
        out[g * NCLS + k] = s;
    }
}

// ---------------- launch ------------------------------------------------------
extern "C" void kernel_launch(void* const* d_in, const int* in_sizes, int n_in,
                              void* d_out, int out_size) {
    const float* x    = (const float*)d_in[0];
    const int*   ei   = (const int*)d_in[1];
    const int*   batch= (const int*)d_in[2];
    const float* W0   = (const float*)d_in[3];
    const float* as0  = (const float*)d_in[4];
    const float* ad0  = (const float*)d_in[5];
    const float* b0   = (const float*)d_in[6];
    const float* W1   = (const float*)d_in[7];
    const float* as1  = (const float*)d_in[8];
    const float* ad1  = (const float*)d_in[9];
    const float* b1   = (const float*)d_in[10];
    const float* W2   = (const float*)d_in[11];
    const float* as2  = (const float*)d_in[12];
    const float* ad2  = (const float*)d_in[13];
    const float* b2   = (const float*)d_in[14];
    const float* Wc   = (const float*)d_in[15];
    const float* bc   = (const float*)d_in[16];
    float* out = (float*)d_out;

    float *pA, *pB;
    cudaGetSymbolAddress((void**)&pA, g_bufA);
    cudaGetSymbolAddress((void**)&pB, g_bufB);

    zero_kernel<<<(NN + 255) / 256, 256>>>();
    hist_kernel<<<(EE + 255) / 256, 256>>>(ei);
    scan_kernel<<<1, 1024>>>();
    scatter_kernel<<<(EE + 255) / 256, 256>>>(ei);

    const int wgrid = (NN * 32 + 255) / 256;

    // layer 0
    dim3 g0((NN + 127) / 128, HC / 64);
    sgemm_kernel<128, 64, 16, 8, 4><<<g0, 256>>>(x, W0, pA, NN, INC, HC);
    alpha_kernel<HEADS, HIDC><<<wgrid, 256>>>(pA, as0, ad0);
    agg_kernel<HEADS, HIDC><<<wgrid, 256>>>(pA, b0, pB);

    // layer 1
    sgemm_kernel<128, 64, 16, 8, 4><<<g0, 256>>>(pB, W1, pA, NN, HC, HC);
    alpha_kernel<HEADS, HIDC><<<wgrid, 256>>>(pA, as1, ad1);
    agg_kernel<HEADS, HIDC><<<wgrid, 256>>>(pA, b1, pB);

    // layer 2 (single head)
    dim3 g2((NN + 127) / 128, 1);
    sgemm_kernel<128, 64, 16, 8, 4><<<g2, 256>>>(pB, W2, pA, NN, HC, HIDC);
    alpha_kernel<1, HIDC><<<wgrid, 256>>>(pA, as2, ad2);
    agg_kernel<1, HIDC><<<wgrid, 256>>>(pA, b2, pB);

    // pool + classify
    pool_kernel<<<(NN * HIDC + 255) / 256, 256>>>(pB, batch);
    cls_kernel<<<GG, 256>>>(Wc, bc, out);
}

// round 2
// speedup vs baseline: 1.0538x; 1.0538x over previous
#include <cuda_runtime.h>
#include <math.h>

#define NN    50000
#define EE    800000
#define INC   128
#define HEADS 4
#define HIDC  64
#define HC    256       // HEADS*HIDC
#define NCLS  200
#define GG    64
#define NEG   0.2f

// ---------------- scratch (static device globals; no allocation) -------------
__device__ float g_bufA[NN * HC];
__device__ float g_bufB[NN * HC];
__device__ float g_as[NN * HEADS];
__device__ float g_ad[NN * HEADS];
__device__ int   g_deg[NN];
__device__ int   g_rowptr[NN + 1];
__device__ int   g_wp[NN];
__device__ int   g_csr[EE];
__device__ float g_pool[GG * HIDC];
__device__ float g_cnt[GG];

__device__ __forceinline__ float leaky(float z) { return z > 0.f ? z : NEG * z; }

// ---------------- graph prep ------------------------------------------------
__global__ void zero_kernel() {
    int tid = blockIdx.x * blockDim.x + threadIdx.x;
    if (tid < NN) g_deg[tid] = 0;
    if (tid < GG * HIDC) g_pool[tid] = 0.f;
    if (tid < GG) g_cnt[tid] = 0.f;
}

__global__ void hist_kernel(const int* __restrict__ ei) {
    int e = blockIdx.x * blockDim.x + threadIdx.x;
    if (e < EE) atomicAdd(&g_deg[ei[EE + e]], 1);
}

__global__ void scan_kernel() {
    __shared__ int sh[1024];
    int t = threadIdx.x;
    const int CHK = (NN + 1023) / 1024;
    int base = t * CHK;
    int s = 0;
    for (int i = 0; i < CHK; i++) {
        int idx = base + i;
        if (idx < NN) s += g_deg[idx];
    }
    sh[t] = s;
    __syncthreads();
    for (int off = 1; off < 1024; off <<= 1) {
        int v = (t >= off) ? sh[t - off] : 0;
        __syncthreads();
        sh[t] += v;
        __syncthreads();
    }
    int run = sh[t] - s;   // exclusive prefix
    for (int i = 0; i < CHK; i++) {
        int idx = base + i;
        if (idx < NN) {
            g_rowptr[idx] = run;
            g_wp[idx] = run;
            run += g_deg[idx];
        }
    }
    if (t == 1023) g_rowptr[NN] = sh[1023];
}

__global__ void scatter_kernel(const int* __restrict__ ei) {
    int e = blockIdx.x * blockDim.x + threadIdx.x;
    if (e < EE) {
        int d = ei[EE + e];
        int p = atomicAdd(&g_wp[d], 1);
        g_csr[p] = ei[e];   // store src
    }
}

// ---------------- double-buffered SGEMM: C[M,Nn] = A[M,K] @ B[K,Nn] ----------
// 256 threads, per-thread TM x TN tile, float4 everywhere.
template <int BM, int BN, int BK, int TM, int TN>
__global__ __launch_bounds__(256) void sgemm2_kernel(
        const float* __restrict__ A, const float* __restrict__ B,
        float* __restrict__ C, int M, int K, int Nn) {
    __shared__ __align__(16) float As[2][BK][BM + 4];
    __shared__ __align__(16) float Bs[2][BK][BN];
    const int bm = blockIdx.x * BM, bn = blockIdx.y * BN;
    const int tid = threadIdx.x;
    const int tr = tid / (BN / TN), tc = tid % (BN / TN);

    constexpr int LA = (BM * BK) / (4 * 256);   // float4 A loads per thread
    constexpr int LB = (BK * BN) / (4 * 256);   // float4 B loads per thread
    float4 ra[LA], rb[LB];

    float acc[TM][TN];
#pragma unroll
    for (int m = 0; m < TM; m++)
#pragma unroll
        for (int n = 0; n < TN; n++) acc[m][n] = 0.f;

    // ---- loaders (global -> regs) ----
    auto loadA = [&](int k0) {
#pragma unroll
        for (int i = 0; i < LA; i++) {
            int idx = i * 256 + tid;
            int row = idx / (BK / 4), c4 = idx % (BK / 4);
            int gr = bm + row;
            if (gr < M)
                ra[i] = *reinterpret_cast<const float4*>(&A[gr * K + k0 + 4 * c4]);
            else
                ra[i] = make_float4(0.f, 0.f, 0.f, 0.f);
        }
#pragma unroll
        for (int i = 0; i < LB; i++) {
            int idx = i * 256 + tid;
            int row = idx / (BN / 4), c4 = idx % (BN / 4);
            rb[i] = *reinterpret_cast<const float4*>(&B[(k0 + row) * Nn + bn + 4 * c4]);
        }
    };
    // ---- regs -> smem (A transposed) ----
    auto store = [&](int buf) {
#pragma unroll
        for (int i = 0; i < LA; i++) {
            int idx = i * 256 + tid;
            int row = idx / (BK / 4), c4 = idx % (BK / 4);
            As[buf][4 * c4 + 0][row] = ra[i].x;
            As[buf][4 * c4 + 1][row] = ra[i].y;
            As[buf][4 * c4 + 2][row] = ra[i].z;
            As[buf][4 * c4 + 3][row] = ra[i].w;
        }
#pragma unroll
        for (int i = 0; i < LB; i++) {
            int idx = i * 256 + tid;
            int row = idx / (BN / 4), c4 = idx % (BN / 4);
            *reinterpret_cast<float4*>(&Bs[buf][row][4 * c4]) = rb[i];
        }
    };

    const int nt = K / BK;
    loadA(0);
    store(0);
    __syncthreads();
    int buf = 0;
    for (int t = 0; t < nt; t++) {
        if (t + 1 < nt) loadA((t + 1) * BK);
#pragma unroll
        for (int k = 0; k < BK; k++) {
            float rm[TM], rn[TN];
#pragma unroll
            for (int m = 0; m < TM; m += 4)
                *reinterpret_cast<float4*>(&rm[m]) =
                    *reinterpret_cast<const float4*>(&As[buf][k][tr * TM + m]);
#pragma unroll
            for (int n = 0; n < TN; n += 4)
                *reinterpret_cast<float4*>(&rn[n]) =
                    *reinterpret_cast<const float4*>(&Bs[buf][k][tc * TN + n]);
#pragma unroll
            for (int m = 0; m < TM; m++)
#pragma unroll
                for (int n = 0; n < TN; n++) acc[m][n] = fmaf(rm[m], rn[n], acc[m][n]);
        }
        if (t + 1 < nt) {
            store(buf ^ 1);
            __syncthreads();
            buf ^= 1;
        }
    }

#pragma unroll
    for (int m = 0; m < TM; m++) {
        int row = bm + tr * TM + m;
        if (row < M) {
#pragma unroll
            for (int n = 0; n < TN; n += 4)
                *reinterpret_cast<float4*>(&C[row * Nn + bn + tc * TN + n]) =
                    *reinterpret_cast<const float4*>(&acc[m][n]);
        }
    }
}

// ---------------- per-node attention logits ----------------------------------
template <int H, int C>
__global__ void alpha_kernel(const float* __restrict__ h, const float* __restrict__ a_s,
                             const float* __restrict__ a_d) {
    int gw = (blockIdx.x * blockDim.x + threadIdx.x) >> 5;
    int lane = threadIdx.x & 31;
    if (gw >= NN) return;
    const int HCc = H * C, PER = HCc / 32;
    float ps[H], pd[H];
#pragma unroll
    for (int hh = 0; hh < H; hh++) { ps[hh] = 0.f; pd[hh] = 0.f; }
#pragma unroll
    for (int j = 0; j < PER; j++) {
        int c = lane + 32 * j;
        float v = h[gw * HCc + c];
        const int hh = (32 * j) / C;
        ps[hh] += v * a_s[c];
        pd[hh] += v * a_d[c];
    }
#pragma unroll
    for (int hh = 0; hh < H; hh++) {
        for (int o = 16; o > 0; o >>= 1) {
            ps[hh] += __shfl_xor_sync(0xffffffffu, ps[hh], o);
            pd[hh] += __shfl_xor_sync(0xffffffffu, pd[hh], o);
        }
    }
    if (lane == 0) {
#pragma unroll
        for (int hh = 0; hh < H; hh++) {
            g_as[gw * H + hh] = ps[hh];
            g_ad[gw * H + hh] = pd[hh];
        }
    }
}

// ---------------- gather-side GAT aggregation (warp per dst node) ------------
template <int H, int C>
__global__ void agg_kernel(const float* __restrict__ h, const float* __restrict__ bias,
                           float* __restrict__ out) {
    const int HCc = H * C, PER = HCc / 32;
    __shared__ float w_sh[8][32 * H];
    __shared__ int   s_sh[8][32];
    const int wid = threadIdx.x >> 5, lane = threadIdx.x & 31;
    const int n = (blockIdx.x * blockDim.x + threadIdx.x) >> 5;
    if (n >= NN) return;

    const int start = g_rowptr[n], end = g_rowptr[n + 1];
    float adv[H], asv[H];
#pragma unroll
    for (int hh = 0; hh < H; hh++) {
        adv[hh] = g_ad[n * H + hh];
        asv[hh] = g_as[n * H + hh];
    }
    // pass 1: max over edges (incl. self loop)
    float m[H];
#pragma unroll
    for (int hh = 0; hh < H; hh++) m[hh] = leaky(asv[hh] + adv[hh]);
    for (int i = start + lane; i < end; i += 32) {
        int s = g_csr[i];
#pragma unroll
        for (int hh = 0; hh < H; hh++)
            m[hh] = fmaxf(m[hh], leaky(g_as[s * H + hh] + adv[hh]));
    }
#pragma unroll
    for (int hh = 0; hh < H; hh++)
        for (int o = 16; o > 0; o >>= 1)
            m[hh] = fmaxf(m[hh], __shfl_xor_sync(0xffffffffu, m[hh], o));

    // pass 2: denom
    float den[H];
#pragma unroll
    for (int hh = 0; hh < H; hh++)
        den[hh] = (lane == 0) ? __expf(leaky(asv[hh] + adv[hh]) - m[hh]) : 0.f;
    for (int i = start + lane; i < end; i += 32) {
        int s = g_csr[i];
#pragma unroll
        for (int hh = 0; hh < H; hh++)
            den[hh] += __expf(leaky(g_as[s * H + hh] + adv[hh]) - m[hh]);
    }
    float inv[H];
#pragma unroll
    for (int hh = 0; hh < H; hh++) {
        for (int o = 16; o > 0; o >>= 1)
            den[hh] += __shfl_xor_sync(0xffffffffu, den[hh], o);
        inv[hh] = 1.f / (den[hh] + 1e-16f);
    }

    // pass 3: weighted gather (self edge first)
    float acc[PER];
    {
        float ws[H];
#pragma unroll
        for (int hh = 0; hh < H; hh++)
            ws[hh] = __expf(leaky(asv[hh] + adv[hh]) - m[hh]) * inv[hh];
#pragma unroll
        for (int j = 0; j < PER; j++) {
            int c = lane + 32 * j;
            acc[j] = h[n * HCc + c] * ws[(32 * j) / C];
        }
    }
    for (int base = start; base < end; base += 32) {
        int i = base + lane;
        if (i < end) {
            int s = g_csr[i];
            s_sh[wid][lane] = s;
#pragma unroll
            for (int hh = 0; hh < H; hh++)
                w_sh[wid][lane * H + hh] =
                    __expf(leaky(g_as[s * H + hh] + adv[hh]) - m[hh]) * inv[hh];
        }
        __syncwarp();
        int cnt = min(32, end - base);
        for (int k = 0; k < cnt; k++) {
            int s = s_sh[wid][k];
#pragma unroll
            for (int j = 0; j < PER; j++) {
                int c = lane + 32 * j;
                acc[j] += h[s * HCc + c] * w_sh[wid][k * H + (32 * j) / C];
            }
        }
        __syncwarp();
    }
    // epilogue: + bias, ELU
#pragma unroll
    for (int j = 0; j < PER; j++) {
        int c = lane + 32 * j;
        float v = acc[j] + bias[c];
        out[n * HCc + c] = v > 0.f ? v : (__expf(v) - 1.f);
    }
}

// ---------------- pooling + classifier ---------------------------------------
__global__ void pool_kernel(const float* __restrict__ h, const int* __restrict__ batch) {
    int tid = blockIdx.x * blockDim.x + threadIdx.x;
    if (tid >= NN * HIDC) return;
    int node = tid / HIDC, c = tid % HIDC;
    int g = batch[node];
    atomicAdd(&g_pool[g * HIDC + c], h[node * HIDC + c]);
    if (c == 0) atomicAdd(&g_cnt[g], 1.f);
}

__global__ void cls_kernel(const float* __restrict__ Wc, const float* __restrict__ bc,
                           float* __restrict__ out) {
    __shared__ float p[HIDC];
    int g = blockIdx.x;
    if (threadIdx.x < HIDC)
        p[threadIdx.x] = g_pool[g * HIDC + threadIdx.x] / fmaxf(g_cnt[g], 1.f);
    __syncthreads();
    for (int k = threadIdx.x; k < NCLS; k += blockDim.x) {
        float s = bc[k];
#pragma unroll
        for (int c = 0; c < HIDC; c++) s += p[c] * Wc[c * NCLS + k];
        out[g * NCLS + k] = s;
    }
}

// ---------------- launch ------------------------------------------------------
extern "C" void kernel_launch(void* const* d_in, const int* in_sizes, int n_in,
                              void* d_out, int out_size) {
    const float* x    = (const float*)d_in[0];
    const int*   ei   = (const int*)d_in[1];
    const int*   batch= (const int*)d_in[2];
    const float* W0   = (const float*)d_in[3];
    const float* as0  = (const float*)d_in[4];
    const float* ad0  = (const float*)d_in[5];
    const float* b0   = (const float*)d_in[6];
    const float* W1   = (const float*)d_in[7];
    const float* as1  = (const float*)d_in[8];
    const float* ad1  = (const float*)d_in[9];
    const float* b1   = (const float*)d_in[10];
    const float* W2   = (const float*)d_in[11];
    const float* as2  = (const float*)d_in[12];
    const float* ad2  = (const float*)d_in[13];
    const float* b2   = (const float*)d_in[14];
    const float* Wc   = (const float*)d_in[15];
    const float* bc   = (const float*)d_in[16];
    float* out = (float*)d_out;

    float *pA, *pB;
    cudaGetSymbolAddress((void**)&pA, g_bufA);
    cudaGetSymbolAddress((void**)&pB, g_bufB);

    zero_kernel<<<(NN + 255) / 256, 256>>>();
    hist_kernel<<<(EE + 255) / 256, 256>>>(ei);
    scan_kernel<<<1, 1024>>>();
    scatter_kernel<<<(EE + 255) / 256, 256>>>(ei);

    const int wgrid = (NN * 32 + 255) / 256;

    // layer 0: [50000,128] @ [128,256]
    dim3 g0((NN + 127) / 128, HC / 128);
    sgemm2_kernel<128, 128, 16, 8, 8><<<g0, 256>>>(x, W0, pA, NN, INC, HC);
    alpha_kernel<HEADS, HIDC><<<wgrid, 256>>>(pA, as0, ad0);
    agg_kernel<HEADS, HIDC><<<wgrid, 256>>>(pA, b0, pB);

    // layer 1: [50000,256] @ [256,256]
    sgemm2_kernel<128, 128, 16, 8, 8><<<g0, 256>>>(pB, W1, pA, NN, HC, HC);
    alpha_kernel<HEADS, HIDC><<<wgrid, 256>>>(pA, as1, ad1);
    agg_kernel<HEADS, HIDC><<<wgrid, 256>>>(pA, b1, pB);

    // layer 2: [50000,256] @ [256,64] (single head)
    dim3 g2((NN + 127) / 128, 1);
    sgemm2_kernel<128, 64, 16, 8, 4><<<g2, 256>>>(pB, W2, pA, NN, HC, HIDC);
    alpha_kernel<1, HIDC><<<wgrid, 256>>>(pA, as2, ad2);
    agg_kernel<1, HIDC><<<wgrid, 256>>>(pA, b2, pB);

    // pool + classify
    pool_kernel<<<(NN * HIDC + 255) / 256, 256>>>(pB, batch);
    cls_kernel<<<GG, 256>>>(Wc, bc, out);
}

// round 3
// speedup vs baseline: 1.4605x; 1.3860x over previous
#include <cuda_runtime.h>
#include <math.h>
#include <stdint.h>

#define NN    50000
#define EE    800000
#define INC   128
#define HEADS 4
#define HIDC  64
#define HC    256       // HEADS*HIDC
#define NCLS  200
#define GG    64
#define NEG   0.2f

// ---------------- scratch (static device globals; no allocation) -------------
__device__ __align__(16) float g_bufA[NN * HC];
__device__ __align__(16) float g_bufB[NN * HC];
__device__ __align__(16) float g_as[NN * HEADS];
__device__ __align__(16) float g_ad[NN * HEADS];
__device__ int   g_deg[NN];
__device__ int   g_rowptr[NN + 1];
__device__ int   g_wp[NN];
__device__ int   g_csr[EE];
__device__ float g_pool[GG * HIDC];
__device__ float g_cnt[GG];

__device__ __forceinline__ float leaky(float z) { return z > 0.f ? z : NEG * z; }

__device__ __forceinline__ uint32_t f2tf32(float f) {
    uint32_t u;
    asm("cvt.rna.tf32.f32 %0, %1;" : "=r"(u) : "f"(f));
    return u;
}

// ---------------- graph prep ------------------------------------------------
__global__ void zero_kernel() {
    int tid = blockIdx.x * blockDim.x + threadIdx.x;
    if (tid < NN) g_deg[tid] = 0;
    if (tid < GG * HIDC) g_pool[tid] = 0.f;
    if (tid < GG) g_cnt[tid] = 0.f;
}

__global__ void hist_kernel(const int* __restrict__ ei) {
    int e = blockIdx.x * blockDim.x + threadIdx.x;
    if (e < EE) atomicAdd(&g_deg[ei[EE + e]], 1);
}

__global__ void scan_kernel() {
    __shared__ int sh[1024];
    int t = threadIdx.x;
    const int CHK = (NN + 1023) / 1024;
    int base = t * CHK;
    int s = 0;
    for (int i = 0; i < CHK; i++) {
        int idx = base + i;
        if (idx < NN) s += g_deg[idx];
    }
    sh[t] = s;
    __syncthreads();
    for (int off = 1; off < 1024; off <<= 1) {
        int v = (t >= off) ? sh[t - off] : 0;
        __syncthreads();
        sh[t] += v;
        __syncthreads();
    }
    int run = sh[t] - s;   // exclusive prefix
    for (int i = 0; i < CHK; i++) {
        int idx = base + i;
        if (idx < NN) {
            g_rowptr[idx] = run;
            g_wp[idx] = run;
            run += g_deg[idx];
        }
    }
    if (t == 1023) g_rowptr[NN] = sh[1023];
}

__global__ void scatter_kernel(const int* __restrict__ ei) {
    int e = blockIdx.x * blockDim.x + threadIdx.x;
    if (e < EE) {
        int d = ei[EE + e];
        int p = atomicAdd(&g_wp[d], 1);
        g_csr[p] = ei[e];   // store src
    }
}

// ---------------- TF32 tensor-core GEMM: C[M,Nn] = A[M,K] @ B[K,Nn] ----------
// 256 threads, 8 warps. Warp tile WM x WN from m16n8k8 tf32 mma.
template <int BM, int BN, int BK, int WM, int WN>
__global__ __launch_bounds__(256) void tgemm_kernel(
        const float* __restrict__ A, const float* __restrict__ B,
        float* __restrict__ C, int M, int K, int Nn) {
    constexpr int PAD = 8;
    __shared__ uint32_t As[2][BK][BM + PAD];   // [k][m], tf32 bits
    __shared__ uint32_t Bs[2][BK][BN + PAD];   // [k][n], tf32 bits
    constexpr int WARPS_N = BN / WN;
    constexpr int MT = WM / 16, NT = WN / 8;

    const int tid = threadIdx.x, wid = tid >> 5, lane = tid & 31;
    const int wm = (wid / WARPS_N) * WM, wn = (wid % WARPS_N) * WN;
    const int bm = blockIdx.x * BM, bn = blockIdx.y * BN;

    float acc[MT][NT][4] = {};

    constexpr int LA = (BM * BK) / (4 * 256);
    constexpr int LB = (BK * BN) / (4 * 256);
    float4 ra[LA], rb[LB];

    auto load = [&](int k0) {
#pragma unroll
        for (int i = 0; i < LA; i++) {
            int idx = i * 256 + tid;
            int r = idx / (BK / 4), c4 = idx % (BK / 4);
            int gr = bm + r;
            ra[i] = (gr < M) ? *reinterpret_cast<const float4*>(&A[gr * K + k0 + 4 * c4])
                             : make_float4(0.f, 0.f, 0.f, 0.f);
        }
#pragma unroll
        for (int i = 0; i < LB; i++) {
            int idx = i * 256 + tid;
            int r = idx / (BN / 4), c4 = idx % (BN / 4);
            rb[i] = *reinterpret_cast<const float4*>(&B[(k0 + r) * Nn + bn + 4 * c4]);
        }
    };
    auto store = [&](int buf) {
#pragma unroll
        for (int i = 0; i < LA; i++) {
            int idx = i * 256 + tid;
            int r = idx / (BK / 4), c4 = idx % (BK / 4);
            As[buf][4 * c4 + 0][r] = f2tf32(ra[i].x);
            As[buf][4 * c4 + 1][r] = f2tf32(ra[i].y);
            As[buf][4 * c4 + 2][r] = f2tf32(ra[i].z);
            As[buf][4 * c4 + 3][r] = f2tf32(ra[i].w);
        }
#pragma unroll
        for (int i = 0; i < LB; i++) {
            int idx = i * 256 + tid;
            int r = idx / (BN / 4), c4 = idx % (BN / 4);
            uint4 b4;
            b4.x = f2tf32(rb[i].x); b4.y = f2tf32(rb[i].y);
            b4.z = f2tf32(rb[i].z); b4.w = f2tf32(rb[i].w);
            *reinterpret_cast<uint4*>(&Bs[buf][r][4 * c4]) = b4;
        }
    };

    const int ntiles = K / BK;
    load(0);
    store(0);
    __syncthreads();
    int buf = 0;
    for (int t = 0; t < ntiles; t++) {
        if (t + 1 < ntiles) load((t + 1) * BK);
#pragma unroll
        for (int ks = 0; ks < BK / 8; ks++) {
            uint32_t af[MT][4], bf[NT][2];
            const int krow = ks * 8 + (lane & 3);
#pragma unroll
            for (int mt = 0; mt < MT; mt++) {
                int m0 = wm + mt * 16 + (lane >> 2);
                af[mt][0] = As[buf][krow][m0];
                af[mt][1] = As[buf][krow][m0 + 8];
                af[mt][2] = As[buf][krow + 4][m0];
                af[mt][3] = As[buf][krow + 4][m0 + 8];
            }
#pragma unroll
            for (int nt = 0; nt < NT; nt++) {
                int n0 = wn + nt * 8 + (lane >> 2);
                bf[nt][0] = Bs[buf][krow][n0];
                bf[nt][1] = Bs[buf][krow + 4][n0];
            }
#pragma unroll
            for (int mt = 0; mt < MT; mt++)
#pragma unroll
                for (int nt = 0; nt < NT; nt++)
                    asm volatile(
                        "mma.sync.aligned.m16n8k8.row.col.f32.tf32.tf32.f32 "
                        "{%0,%1,%2,%3},{%4,%5,%6,%7},{%8,%9},{%0,%1,%2,%3};"
                        : "+f"(acc[mt][nt][0]), "+f"(acc[mt][nt][1]),
                          "+f"(acc[mt][nt][2]), "+f"(acc[mt][nt][3])
                        : "r"(af[mt][0]), "r"(af[mt][1]), "r"(af[mt][2]), "r"(af[mt][3]),
                          "r"(bf[nt][0]), "r"(bf[nt][1]));
        }
        if (t + 1 < ntiles) {
            store(buf ^ 1);
            __syncthreads();
            buf ^= 1;
        }
    }

    // epilogue: c0/c1 at (row, 2*(lane&3)), c2/c3 at row+8
#pragma unroll
    for (int mt = 0; mt < MT; mt++) {
        int r0 = bm + wm + mt * 16 + (lane >> 2);
#pragma unroll
        for (int nt = 0; nt < NT; nt++) {
            int c0 = bn + wn + nt * 8 + 2 * (lane & 3);
            if (r0 < M)
                *reinterpret_cast<float2*>(&C[r0 * Nn + c0]) =
                    make_float2(acc[mt][nt][0], acc[mt][nt][1]);
            if (r0 + 8 < M)
                *reinterpret_cast<float2*>(&C[(r0 + 8) * Nn + c0]) =
                    make_float2(acc[mt][nt][2], acc[mt][nt][3]);
        }
    }
}

// ---------------- per-node attention logits ----------------------------------
template <int H, int C>
__global__ void alpha_kernel(const float* __restrict__ h, const float* __restrict__ a_s,
                             const float* __restrict__ a_d) {
    int gw = (blockIdx.x * blockDim.x + threadIdx.x) >> 5;
    int lane = threadIdx.x & 31;
    if (gw >= NN) return;
    const int HCc = H * C, PER = HCc / 32;
    float ps[H], pd[H];
#pragma unroll
    for (int hh = 0; hh < H; hh++) { ps[hh] = 0.f; pd[hh] = 0.f; }
#pragma unroll
    for (int j = 0; j < PER; j++) {
        int c = lane + 32 * j;
        float v = h[gw * HCc + c];
        const int hh = (32 * j) / C;
        ps[hh] += v * a_s[c];
        pd[hh] += v * a_d[c];
    }
#pragma unroll
    for (int hh = 0; hh < H; hh++) {
        for (int o = 16; o > 0; o >>= 1) {
            ps[hh] += __shfl_xor_sync(0xffffffffu, ps[hh], o);
            pd[hh] += __shfl_xor_sync(0xffffffffu, pd[hh], o);
        }
    }
    if (lane == 0) {
#pragma unroll
        for (int hh = 0; hh < H; hh++) {
            g_as[gw * H + hh] = ps[hh];
            g_ad[gw * H + hh] = pd[hh];
        }
    }
}

// -------- gather-side GAT aggregation, H=4 C=64, float4-vectorized -----------
__global__ void agg4_kernel(const float* __restrict__ h, const float* __restrict__ bias,
                            float* __restrict__ out) {
    __shared__ float w_sh[8][32 * HEADS];
    __shared__ int   s_sh[8][32];
    const int wid = threadIdx.x >> 5, lane = threadIdx.x & 31;
    const int n = (blockIdx.x * blockDim.x + threadIdx.x) >> 5;
    if (n >= NN) return;

    const int start = g_rowptr[n], end = g_rowptr[n + 1];
    const float4 adv = *reinterpret_cast<const float4*>(&g_ad[n * 4]);
    const float4 asv = *reinterpret_cast<const float4*>(&g_as[n * 4]);
    const float ad[4] = {adv.x, adv.y, adv.z, adv.w};
    const float as_[4] = {asv.x, asv.y, asv.z, asv.w};

    // pass 1: max (incl. self loop)
    float m[4];
#pragma unroll
    for (int hh = 0; hh < 4; hh++) m[hh] = leaky(as_[hh] + ad[hh]);
    for (int i = start + lane; i < end; i += 32) {
        int s = g_csr[i];
        float4 sa = *reinterpret_cast<const float4*>(&g_as[s * 4]);
        m[0] = fmaxf(m[0], leaky(sa.x + ad[0]));
        m[1] = fmaxf(m[1], leaky(sa.y + ad[1]));
        m[2] = fmaxf(m[2], leaky(sa.z + ad[2]));
        m[3] = fmaxf(m[3], leaky(sa.w + ad[3]));
    }
#pragma unroll
    for (int hh = 0; hh < 4; hh++)
        for (int o = 16; o > 0; o >>= 1)
            m[hh] = fmaxf(m[hh], __shfl_xor_sync(0xffffffffu, m[hh], o));

    // pass 2: denom
    float den[4];
#pragma unroll
    for (int hh = 0; hh < 4; hh++)
        den[hh] = (lane == 0) ? __expf(leaky(as_[hh] + ad[hh]) - m[hh]) : 0.f;
    for (int i = start + lane; i < end; i += 32) {
        int s = g_csr[i];
        float4 sa = *reinterpret_cast<const float4*>(&g_as[s * 4]);
        den[0] += __expf(leaky(sa.x + ad[0]) - m[0]);
        den[1] += __expf(leaky(sa.y + ad[1]) - m[1]);
        den[2] += __expf(leaky(sa.z + ad[2]) - m[2]);
        den[3] += __expf(leaky(sa.w + ad[3]) - m[3]);
    }
    float inv[4];
#pragma unroll
    for (int hh = 0; hh < 4; hh++) {
        for (int o = 16; o > 0; o >>= 1)
            den[hh] += __shfl_xor_sync(0xffffffffu, den[hh], o);
        inv[hh] = 1.f / (den[hh] + 1e-16f);
    }

    // pass 3: weighted gather. Lane covers c = 4*lane + 128*j, j in {0,1}.
    const int h0 = lane >> 4;           // head for j=0
    float4 acc0, acc1;
    {
        float ws[4];
#pragma unroll
        for (int hh = 0; hh < 4; hh++)
            ws[hh] = __expf(leaky(as_[hh] + ad[hh]) - m[hh]) * inv[hh];
        float4 v0 = *reinterpret_cast<const float4*>(&h[n * HC + 4 * lane]);
        float4 v1 = *reinterpret_cast<const float4*>(&h[n * HC + 4 * lane + 128]);
        float w0 = ws[h0], w1 = ws[h0 + 2];
        acc0 = make_float4(v0.x * w0, v0.y * w0, v0.z * w0, v0.w * w0);
        acc1 = make_float4(v1.x * w1, v1.y * w1, v1.z * w1, v1.w * w1);
    }
    for (int base = start; base < end; base += 32) {
        int i = base + lane;
        if (i < end) {
            int s = g_csr[i];
            s_sh[wid][lane] = s;
            float4 sa = *reinterpret_cast<const float4*>(&g_as[s * 4]);
            w_sh[wid][lane * 4 + 0] = __expf(leaky(sa.x + ad[0]) - m[0]) * inv[0];
            w_sh[wid][lane * 4 + 1] = __expf(leaky(sa.y + ad[1]) - m[1]) * inv[1];
            w_sh[wid][lane * 4 + 2] = __expf(leaky(sa.z + ad[2]) - m[2]) * inv[2];
            w_sh[wid][lane * 4 + 3] = __expf(leaky(sa.w + ad[3]) - m[3]) * inv[3];
        }
        __syncwarp();
        int cnt = min(32, end - base);
        for (int k = 0; k < cnt; k++) {
            int s = s_sh[wid][k];
            float w0 = w_sh[wid][k * 4 + h0];
            float w1 = w_sh[wid][k * 4 + h0 + 2];
            float4 v0 = *reinterpret_cast<const float4*>(&h[s * HC + 4 * lane]);
            float4 v1 = *reinterpret_cast<const float4*>(&h[s * HC + 4 * lane + 128]);
            acc0.x = fmaf(v0.x, w0, acc0.x); acc0.y = fmaf(v0.y, w0, acc0.y);
            acc0.z = fmaf(v0.z, w0, acc0.z); acc0.w = fmaf(v0.w, w0, acc0.w);
            acc1.x = fmaf(v1.x, w1, acc1.x); acc1.y = fmaf(v1.y, w1, acc1.y);
            acc1.z = fmaf(v1.z, w1, acc1.z); acc1.w = fmaf(v1.w, w1, acc1.w);
        }
        __syncwarp();
    }
    // epilogue: + bias, ELU
    float4 b0 = *reinterpret_cast<const float4*>(&bias[4 * lane]);
    float4 b1 = *reinterpret_cast<const float4*>(&bias[4 * lane + 128]);
    float4 o0, o1;
    o0.x = acc0.x + b0.x; o0.y = acc0.y + b0.y; o0.z = acc0.z + b0.z; o0.w = acc0.w + b0.w;
    o1.x = acc1.x + b1.x; o1.y = acc1.y + b1.y; o1.z = acc1.z + b1.z; o1.w = acc1.w + b1.w;
    o0.x = o0.x > 0.f ? o0.x : (__expf(o0.x) - 1.f);
    o0.y = o0.y > 0.f ? o0.y : (__expf(o0.y) - 1.f);
    o0.z = o0.z > 0.f ? o0.z : (__expf(o0.z) - 1.f);
    o0.w = o0.w > 0.f ? o0.w : (__expf(o0.w) - 1.f);
    o1.x = o1.x > 0.f ? o1.x : (__expf(o1.x) - 1.f);
    o1.y = o1.y > 0.f ? o1.y : (__expf(o1.y) - 1.f);
    o1.z = o1.z > 0.f ? o1.z : (__expf(o1.z) - 1.f);
    o1.w = o1.w > 0.f ? o1.w : (__expf(o1.w) - 1.f);
    *reinterpret_cast<float4*>(&out[n * HC + 4 * lane]) = o0;
    *reinterpret_cast<float4*>(&out[n * HC + 4 * lane + 128]) = o1;
}

// ---------------- generic scalar aggregation (used for H=1 layer) ------------
template <int H, int C>
__global__ void agg_kernel(const float* __restrict__ h, const float* __restrict__ bias,
                           float* __restrict__ out) {
    const int HCc = H * C, PER = HCc / 32;
    __shared__ float w_sh[8][32 * H];
    __shared__ int   s_sh[8][32];
    const int wid = threadIdx.x >> 5, lane = threadIdx.x & 31;
    const int n = (blockIdx.x * blockDim.x + threadIdx.x) >> 5;
    if (n >= NN) return;

    const int start = g_rowptr[n], end = g_rowptr[n + 1];
    float adv[H], asv[H];
#pragma unroll
    for (int hh = 0; hh < H; hh++) {
        adv[hh] = g_ad[n * H + hh];
        asv[hh] = g_as[n * H + hh];
    }
    float m[H];
#pragma unroll
    for (int hh = 0; hh < H; hh++) m[hh] = leaky(asv[hh] + adv[hh]);
    for (int i = start + lane; i < end; i += 32) {
        int s = g_csr[i];
#pragma unroll
        for (int hh = 0; hh < H; hh++)
            m[hh] = fmaxf(m[hh], leaky(g_as[s * H + hh] + adv[hh]));
    }
#pragma unroll
    for (int hh = 0; hh < H; hh++)
        for (int o = 16; o > 0; o >>= 1)
            m[hh] = fmaxf(m[hh], __shfl_xor_sync(0xffffffffu, m[hh], o));

    float den[H];
#pragma unroll
    for (int hh = 0; hh < H; hh++)
        den[hh] = (lane == 0) ? __expf(leaky(asv[hh] + adv[hh]) - m[hh]) : 0.f;
    for (int i = start + lane; i < end; i += 32) {
        int s = g_csr[i];
#pragma unroll
        for (int hh = 0; hh < H; hh++)
            den[hh] += __expf(leaky(g_as[s * H + hh] + adv[hh]) - m[hh]);
    }
    float inv[H];
#pragma unroll
    for (int hh = 0; hh < H; hh++) {
        for (int o = 16; o > 0; o >>= 1)
            den[hh] += __shfl_xor_sync(0xffffffffu, den[hh], o);
        inv[hh] = 1.f / (den[hh] + 1e-16f);
    }

    float acc[PER];
    {
        float ws[H];
#pragma unroll
        for (int hh = 0; hh < H; hh++)
            ws[hh] = __expf(leaky(asv[hh] + adv[hh]) - m[hh]) * inv[hh];
#pragma unroll
        for (int j = 0; j < PER; j++) {
            int c = lane + 32 * j;
            acc[j] = h[n * HCc + c] * ws[(32 * j) / C];
        }
    }
    for (int base = start; base < end; base += 32) {
        int i = base + lane;
        if (i < end) {
            int s = g_csr[i];
            s_sh[wid][lane] = s;
#pragma unroll
            for (int hh = 0; hh < H; hh++)
                w_sh[wid][lane * H + hh] =
                    __expf(leaky(g_as[s * H + hh] + adv[hh]) - m[hh]) * inv[hh];
        }
        __syncwarp();
        int cnt = min(32, end - base);
        for (int k = 0; k < cnt; k++) {
            int s = s_sh[wid][k];
#pragma unroll
            for (int j = 0; j < PER; j++) {
                int c = lane + 32 * j;
                acc[j] += h[s * HCc + c] * w_sh[wid][k * H + (32 * j) / C];
            }
        }
        __syncwarp();
    }
#pragma unroll
    for (int j = 0; j < PER; j++) {
        int c = lane + 32 * j;
        float v = acc[j] + bias[c];
        out[n * HCc + c] = v > 0.f ? v : (__expf(v) - 1.f);
    }
}

// ---------------- pooling + classifier ---------------------------------------
__global__ void pool_kernel(const float* __restrict__ h, const int* __restrict__ batch) {
    int tid = blockIdx.x * blockDim.x + threadIdx.x;
    if (tid >= NN * HIDC) return;
    int node = tid / HIDC, c = tid % HIDC;
    int g = batch[node];
    atomicAdd(&g_pool[g * HIDC + c], h[node * HIDC + c]);
    if (c == 0) atomicAdd(&g_cnt[g], 1.f);
}

__global__ void cls_kernel(const float* __restrict__ Wc, const float* __restrict__ bc,
                           float* __restrict__ out) {
    __shared__ float p[HIDC];
    int g = blockIdx.x;
    if (threadIdx.x < HIDC)
        p[threadIdx.x] = g_pool[g * HIDC + threadIdx.x] / fmaxf(g_cnt[g], 1.f);
    __syncthreads();
    for (int k = threadIdx.x; k < NCLS; k += blockDim.x) {
        float s = bc[k];
#pragma unroll
        for (int c = 0; c < HIDC; c++) s += p[c] * Wc[c * NCLS + k];
        out[g * NCLS + k] = s;
    }
}

// ---------------- launch ------------------------------------------------------
extern "C" void kernel_launch(void* const* d_in, const int* in_sizes, int n_in,
                              void* d_out, int out_size) {
    const float* x    = (const float*)d_in[0];
    const int*   ei   = (const int*)d_in[1];
    const int*   batch= (const int*)d_in[2];
    const float* W0   = (const float*)d_in[3];
    const float* as0  = (const float*)d_in[4];
    const float* ad0  = (const float*)d_in[5];
    const float* b0   = (const float*)d_in[6];
    const float* W1   = (const float*)d_in[7];
    const float* as1  = (const float*)d_in[8];
    const float* ad1  = (const float*)d_in[9];
    const float* b1   = (const float*)d_in[10];
    const float* W2   = (const float*)d_in[11];
    const float* as2  = (const float*)d_in[12];
    const float* ad2  = (const float*)d_in[13];
    const float* b2   = (const float*)d_in[14];
    const float* Wc   = (const float*)d_in[15];
    const float* bc   = (const float*)d_in[16];
    float* out = (float*)d_out;

    float *pA, *pB;
    cudaGetSymbolAddress((void**)&pA, g_bufA);
    cudaGetSymbolAddress((void**)&pB, g_bufB);

    zero_kernel<<<(NN + 255) / 256, 256>>>();
    hist_kernel<<<(EE + 255) / 256, 256>>>(ei);
    scan_kernel<<<1, 1024>>>();
    scatter_kernel<<<(EE + 255) / 256, 256>>>(ei);

    const int wgrid = (NN * 32 + 255) / 256;

    // layer 0: [50000,128] @ [128,256]
    dim3 g0((NN + 127) / 128, HC / 128);
    tgemm_kernel<128, 128, 16, 64, 32><<<g0, 256>>>(x, W0, pA, NN, INC, HC);
    alpha_kernel<HEADS, HIDC><<<wgrid, 256>>>(pA, as0, ad0);
    agg4_kernel<<<wgrid, 256>>>(pA, b0, pB);

    // layer 1: [50000,256] @ [256,256]
    tgemm_kernel<128, 128, 16, 64, 32><<<g0, 256>>>(pB, W1, pA, NN, HC, HC);
    alpha_kernel<HEADS, HIDC><<<wgrid, 256>>>(pA, as1, ad1);
    agg4_kernel<<<wgrid, 256>>>(pA, b1, pB);

    // layer 2: [50000,256] @ [256,64] (single head)
    dim3 g2((NN + 127) / 128, 1);
    tgemm_kernel<128, 64, 16, 32, 32><<<g2, 256>>>(pB, W2, pA, NN, HC, HIDC);
    alpha_kernel<1, HIDC><<<wgrid, 256>>>(pA, as2, ad2);
    agg_kernel<1, HIDC><<<wgrid, 256>>>(pA, b2, pB);

    // pool + classify
    pool_kernel<<<(NN * HIDC + 255) / 256, 256>>>(pB, batch);
    cls_kernel<<<GG, 256>>>(Wc, bc, out);
}

// round 4
// speedup vs baseline: 1.9098x; 1.3076x over previous
#include <cuda_runtime.h>
#include <math.h>
#include <stdint.h>

#define NN    50000
#define EE    800000
#define INC   128
#define HEADS 4
#define HIDC  64
#define HC    256       // HEADS*HIDC
#define NCLS  200
#define GG    64
#define NEG   0.2f
#define SCANB 49        // ceil(NN/1024)

// ---------------- scratch (static device globals; no allocation) -------------
__device__ __align__(16) float g_bufA[NN * HC];
__device__ __align__(16) float g_bufB[NN * HC];
__device__ __align__(16) float g_as0[NN * HEADS];
__device__ __align__(16) float g_ad0[NN * HEADS];
__device__ __align__(16) float g_as1[NN * HEADS];
__device__ __align__(16) float g_ad1[NN * HEADS];
__device__ float g_as2[NN];
__device__ float g_ad2[NN];
__device__ int   g_deg[NN];
__device__ int   g_rowptr[NN + 1];
__device__ int   g_wp[NN];
__device__ int   g_csr[EE];
__device__ int   g_bsum[64];
__device__ float g_pool[GG * HIDC];
__device__ float g_cnt[GG];

__device__ __forceinline__ float leaky(float z) { return z > 0.f ? z : NEG * z; }

__device__ __forceinline__ uint32_t f2tf32(float f) {
    uint32_t u;
    asm("cvt.rna.tf32.f32 %0, %1;" : "=r"(u) : "f"(f));
    return u;
}

// ---------------- graph prep ------------------------------------------------
__global__ void zero_kernel() {
    int tid = blockIdx.x * blockDim.x + threadIdx.x;
    if (tid < NN) {
        g_deg[tid] = 0;
        const float4 z4 = make_float4(0.f, 0.f, 0.f, 0.f);
        *reinterpret_cast<float4*>(&g_as0[4 * tid]) = z4;
        *reinterpret_cast<float4*>(&g_ad0[4 * tid]) = z4;
        *reinterpret_cast<float4*>(&g_as1[4 * tid]) = z4;
        *reinterpret_cast<float4*>(&g_ad1[4 * tid]) = z4;
        g_as2[tid] = 0.f;
        g_ad2[tid] = 0.f;
    }
    if (tid < GG * HIDC) g_pool[tid] = 0.f;
    if (tid < GG) g_cnt[tid] = 0.f;
}

__global__ void hist_kernel(const int* __restrict__ ei) {
    int e = blockIdx.x * blockDim.x + threadIdx.x;
    if (e < EE) atomicAdd(&g_deg[ei[EE + e]], 1);
}

// block-local exclusive scan; write local result + block sums
__global__ void scan1_kernel() {
    __shared__ int sh[1024];
    int t = threadIdx.x;
    int idx = blockIdx.x * 1024 + t;
    int v = (idx < NN) ? g_deg[idx] : 0;
    sh[t] = v;
    __syncthreads();
    for (int off = 1; off < 1024; off <<= 1) {
        int u = (t >= off) ? sh[t - off] : 0;
        __syncthreads();
        sh[t] += u;
        __syncthreads();
    }
    if (idx < NN) g_rowptr[idx] = sh[t] - v;   // local exclusive
    if (t == 1023) g_bsum[blockIdx.x] = sh[1023];
}

// exclusive scan of block sums (SCANB <= 64)
__global__ void scan2_kernel() {
    __shared__ int sh[64];
    int t = threadIdx.x;
    int v = (t < SCANB) ? g_bsum[t] : 0;
    sh[t] = v;
    __syncthreads();
    for (int off = 1; off < 64; off <<= 1) {
        int u = (t >= off) ? sh[t - off] : 0;
        __syncthreads();
        sh[t] += u;
        __syncthreads();
    }
    g_bsum[t] = sh[t] - v;
}

__global__ void scan3_kernel() {
    int idx = blockIdx.x * 1024 + threadIdx.x;
    if (idx < NN) {
        int r = g_rowptr[idx] + g_bsum[blockIdx.x];
        g_rowptr[idx] = r;
        g_wp[idx] = r;
        if (idx == NN - 1) g_rowptr[NN] = r + g_deg[idx];
    }
}

__global__ void scatter_kernel(const int* __restrict__ ei) {
    int e = blockIdx.x * blockDim.x + threadIdx.x;
    if (e < EE) {
        int d = ei[EE + e];
        int p = atomicAdd(&g_wp[d], 1);
        g_csr[p] = ei[e];   // store src
    }
}

// ------- TF32 tensor-core GEMM + fused attention-logit epilogue --------------
// C = A @ B; also accumulates gas[row,head] += sum_c C[row,c]*a_s[c],
// gad likewise (heads are 64-col groups; each warp tile sits inside one head).
template <int BM, int BN, int BK, int WM, int WN, int H>
__global__ __launch_bounds__(256) void tgemm_kernel(
        const float* __restrict__ A, const float* __restrict__ B,
        float* __restrict__ C, int M, int K, int Nn,
        const float* __restrict__ a_s, const float* __restrict__ a_d,
        float* __restrict__ gas, float* __restrict__ gad) {
    constexpr int PAD = 8;
    __shared__ uint32_t As[2][BK][BM + PAD];
    __shared__ uint32_t Bs[2][BK][BN + PAD];
    constexpr int WARPS_N = BN / WN;
    constexpr int MT = WM / 16, NT = WN / 8;

    const int tid = threadIdx.x, wid = tid >> 5, lane = tid & 31;
    const int wm = (wid / WARPS_N) * WM, wn = (wid % WARPS_N) * WN;
    const int bm = blockIdx.x * BM, bn = blockIdx.y * BN;

    float acc[MT][NT][4] = {};

    constexpr int LA = (BM * BK) / (4 * 256);
    constexpr int LB = (BK * BN) / (4 * 256);
    float4 ra[LA], rb[LB];

    auto load = [&](int k0) {
#pragma unroll
        for (int i = 0; i < LA; i++) {
            int idx = i * 256 + tid;
            int r = idx / (BK / 4), c4 = idx % (BK / 4);
            int gr = bm + r;
            ra[i] = (gr < M) ? *reinterpret_cast<const float4*>(&A[gr * K + k0 + 4 * c4])
                             : make_float4(0.f, 0.f, 0.f, 0.f);
        }
#pragma unroll
        for (int i = 0; i < LB; i++) {
            int idx = i * 256 + tid;
            int r = idx / (BN / 4), c4 = idx % (BN / 4);
            rb[i] = *reinterpret_cast<const float4*>(&B[(k0 + r) * Nn + bn + 4 * c4]);
        }
    };
    auto store = [&](int buf) {
#pragma unroll
        for (int i = 0; i < LA; i++) {
            int idx = i * 256 + tid;
            int r = idx / (BK / 4), c4 = idx % (BK / 4);
            As[buf][4 * c4 + 0][r] = f2tf32(ra[i].x);
            As[buf][4 * c4 + 1][r] = f2tf32(ra[i].y);
            As[buf][4 * c4 + 2][r] = f2tf32(ra[i].z);
            As[buf][4 * c4 + 3][r] = f2tf32(ra[i].w);
        }
#pragma unroll
        for (int i = 0; i < LB; i++) {
            int idx = i * 256 + tid;
            int r = idx / (BN / 4), c4 = idx % (BN / 4);
            uint4 b4;
            b4.x = f2tf32(rb[i].x); b4.y = f2tf32(rb[i].y);
            b4.z = f2tf32(rb[i].z); b4.w = f2tf32(rb[i].w);
            *reinterpret_cast<uint4*>(&Bs[buf][r][4 * c4]) = b4;
        }
    };

    const int ntiles = K / BK;
    load(0);
    store(0);
    __syncthreads();
    int buf = 0;
    for (int t = 0; t < ntiles; t++) {
        if (t + 1 < ntiles) load((t + 1) * BK);
#pragma unroll
        for (int ks = 0; ks < BK / 8; ks++) {
            uint32_t af[MT][4], bf[NT][2];
            const int krow = ks * 8 + (lane & 3);
#pragma unroll
            for (int mt = 0; mt < MT; mt++) {
                int m0 = wm + mt * 16 + (lane >> 2);
                af[mt][0] = As[buf][krow][m0];
                af[mt][1] = As[buf][krow][m0 + 8];
                af[mt][2] = As[buf][krow + 4][m0];
                af[mt][3] = As[buf][krow + 4][m0 + 8];
            }
#pragma unroll
            for (int nt = 0; nt < NT; nt++) {
                int n0 = wn + nt * 8 + (lane >> 2);
                bf[nt][0] = Bs[buf][krow][n0];
                bf[nt][1] = Bs[buf][krow + 4][n0];
            }
#pragma unroll
            for (int mt = 0; mt < MT; mt++)
#pragma unroll
                for (int nt = 0; nt < NT; nt++)
                    asm volatile(
                        "mma.sync.aligned.m16n8k8.row.col.f32.tf32.tf32.f32 "
                        "{%0,%1,%2,%3},{%4,%5,%6,%7},{%8,%9},{%0,%1,%2,%3};"
                        : "+f"(acc[mt][nt][0]), "+f"(acc[mt][nt][1]),
                          "+f"(acc[mt][nt][2]), "+f"(acc[mt][nt][3])
                        : "r"(af[mt][0]), "r"(af[mt][1]), "r"(af[mt][2]), "r"(af[mt][3]),
                          "r"(bf[nt][0]), "r"(bf[nt][1]));
        }
        if (t + 1 < ntiles) {
            store(buf ^ 1);
            __syncthreads();
            buf ^= 1;
        }
    }

    // attention-vector fragments for this thread's columns
    float asr[NT][2], adr[NT][2];
#pragma unroll
    for (int nt = 0; nt < NT; nt++) {
#pragma unroll
        for (int j = 0; j < 2; j++) {
            int c = bn + wn + nt * 8 + 2 * (lane & 3) + j;
            asr[nt][j] = a_s[c];
            adr[nt][j] = a_d[c];
        }
    }
    const int head = (H == 1) ? 0 : ((bn + wn) >> 6);

    // epilogue: store C, accumulate per-row logit partials
#pragma unroll
    for (int mt = 0; mt < MT; mt++) {
#pragma unroll
        for (int half = 0; half < 2; half++) {
            int row = bm + wm + mt * 16 + (lane >> 2) + half * 8;
            float ps = 0.f, pd = 0.f;
            if (row < M) {
#pragma unroll
                for (int nt = 0; nt < NT; nt++) {
                    int c0 = bn + wn + nt * 8 + 2 * (lane & 3);
                    float v0 = acc[mt][nt][half * 2 + 0];
                    float v1 = acc[mt][nt][half * 2 + 1];
                    *reinterpret_cast<float2*>(&C[row * Nn + c0]) = make_float2(v0, v1);
                    ps = fmaf(v0, asr[nt][0], ps); ps = fmaf(v1, asr[nt][1], ps);
                    pd = fmaf(v0, adr[nt][0], pd); pd = fmaf(v1, adr[nt][1], pd);
                }
            }
            ps += __shfl_xor_sync(0xffffffffu, ps, 1);
            ps += __shfl_xor_sync(0xffffffffu, ps, 2);
            pd += __shfl_xor_sync(0xffffffffu, pd, 1);
            pd += __shfl_xor_sync(0xffffffffu, pd, 2);
            if ((lane & 3) == 0 && row < M) {
                atomicAdd(&gas[row * H + head], ps);
                atomicAdd(&gad[row * H + head], pd);
            }
        }
    }
}

// -------- single-pass gather aggregation, H=4 C=64, float4-vectorized --------
__global__ void agg4_kernel(const float* __restrict__ h, const float* __restrict__ bias,
                            float* __restrict__ out,
                            const float* __restrict__ gas, const float* __restrict__ gad) {
    __shared__ float w_sh[8][32 * HEADS];
    __shared__ int   s_sh[8][32];
    const int wid = threadIdx.x >> 5, lane = threadIdx.x & 31;
    const int n = (blockIdx.x * blockDim.x + threadIdx.x) >> 5;
    if (n >= NN) return;

    const int start = g_rowptr[n], end = g_rowptr[n + 1];
    const float4 adv = *reinterpret_cast<const float4*>(&gad[n * 4]);
    const float4 asv = *reinterpret_cast<const float4*>(&gas[n * 4]);
    const float ad[4] = {adv.x, adv.y, adv.z, adv.w};

    // self-loop weight
    float wself[4];
    wself[0] = __expf(leaky(asv.x + ad[0]));
    wself[1] = __expf(leaky(asv.y + ad[1]));
    wself[2] = __expf(leaky(asv.z + ad[2]));
    wself[3] = __expf(leaky(asv.w + ad[3]));

    const int h0 = lane >> 4;          // head for j=0 block (cols 4*lane)
    float4 acc0, acc1;
    {
        float4 v0 = *reinterpret_cast<const float4*>(&h[n * HC + 4 * lane]);
        float4 v1 = *reinterpret_cast<const float4*>(&h[n * HC + 4 * lane + 128]);
        float w0 = wself[h0], w1 = wself[h0 + 2];
        acc0 = make_float4(v0.x * w0, v0.y * w0, v0.z * w0, v0.w * w0);
        acc1 = make_float4(v1.x * w1, v1.y * w1, v1.z * w1, v1.w * w1);
    }
    float den[4];
#pragma unroll
    for (int hh = 0; hh < 4; hh++) den[hh] = (lane == 0) ? wself[hh] : 0.f;

    for (int base = start; base < end; base += 32) {
        int i = base + lane;
        if (i < end) {
            int s = g_csr[i];
            s_sh[wid][lane] = s;
            float4 sa = *reinterpret_cast<const float4*>(&gas[s * 4]);
            float w0 = __expf(leaky(sa.x + ad[0]));
            float w1 = __expf(leaky(sa.y + ad[1]));
            float w2 = __expf(leaky(sa.z + ad[2]));
            float w3 = __expf(leaky(sa.w + ad[3]));
            w_sh[wid][lane * 4 + 0] = w0;
            w_sh[wid][lane * 4 + 1] = w1;
            w_sh[wid][lane * 4 + 2] = w2;
            w_sh[wid][lane * 4 + 3] = w3;
            den[0] += w0; den[1] += w1; den[2] += w2; den[3] += w3;
        }
        __syncwarp();
        int cnt = min(32, end - base);
        for (int k = 0; k < cnt; k++) {
            int s = s_sh[wid][k];
            float w0 = w_sh[wid][k * 4 + h0];
            float w1 = w_sh[wid][k * 4 + h0 + 2];
            float4 v0 = *reinterpret_cast<const float4*>(&h[s * HC + 4 * lane]);
            float4 v1 = *reinterpret_cast<const float4*>(&h[s * HC + 4 * lane + 128]);
            acc0.x = fmaf(v0.x, w0, acc0.x); acc0.y = fmaf(v0.y, w0, acc0.y);
            acc0.z = fmaf(v0.z, w0, acc0.z); acc0.w = fmaf(v0.w, w0, acc0.w);
            acc1.x = fmaf(v1.x, w1, acc1.x); acc1.y = fmaf(v1.y, w1, acc1.y);
            acc1.z = fmaf(v1.z, w1, acc1.z); acc1.w = fmaf(v1.w, w1, acc1.w);
        }
        __syncwarp();
    }
#pragma unroll
    for (int hh = 0; hh < 4; hh++)
        for (int o = 16; o > 0; o >>= 1)
            den[hh] += __shfl_xor_sync(0xffffffffu, den[hh], o);
    float i0 = 1.f / (den[h0] + 1e-16f);
    float i1 = 1.f / (den[h0 + 2] + 1e-16f);

    float4 b0 = *reinterpret_cast<const float4*>(&bias[4 * lane]);
    float4 b1 = *reinterpret_cast<const float4*>(&bias[4 * lane + 128]);
    float4 o0, o1;
    o0.x = fmaf(acc0.x, i0, b0.x); o0.y = fmaf(acc0.y, i0, b0.y);
    o0.z = fmaf(acc0.z, i0, b0.z); o0.w = fmaf(acc0.w, i0, b0.w);
    o1.x = fmaf(acc1.x, i1, b1.x); o1.y = fmaf(acc1.y, i1, b1.y);
    o1.z = fmaf(acc1.z, i1, b1.z); o1.w = fmaf(acc1.w, i1, b1.w);
    o0.x = o0.x > 0.f ? o0.x : (__expf(o0.x) - 1.f);
    o0.y = o0.y > 0.f ? o0.y : (__expf(o0.y) - 1.f);
    o0.z = o0.z > 0.f ? o0.z : (__expf(o0.z) - 1.f);
    o0.w = o0.w > 0.f ? o0.w : (__expf(o0.w) - 1.f);
    o1.x = o1.x > 0.f ? o1.x : (__expf(o1.x) - 1.f);
    o1.y = o1.y > 0.f ? o1.y : (__expf(o1.y) - 1.f);
    o1.z = o1.z > 0.f ? o1.z : (__expf(o1.z) - 1.f);
    o1.w = o1.w > 0.f ? o1.w : (__expf(o1.w) - 1.f);
    *reinterpret_cast<float4*>(&out[n * HC + 4 * lane]) = o0;
    *reinterpret_cast<float4*>(&out[n * HC + 4 * lane + 128]) = o1;
}

// ---- single-pass aggregation, H=1 C=64, fused global-mean-pool epilogue -----
__global__ void agg1_kernel(const float* __restrict__ h, const float* __restrict__ bias,
                            const int* __restrict__ batch,
                            const float* __restrict__ gas, const float* __restrict__ gad) {
    __shared__ float w_sh[8][32];
    __shared__ int   s_sh[8][32];
    const int wid = threadIdx.x >> 5, lane = threadIdx.x & 31;
    const int n = (blockIdx.x * blockDim.x + threadIdx.x) >> 5;
    if (n >= NN) return;

    const int start = g_rowptr[n], end = g_rowptr[n + 1];
    const float adv = gad[n];
    const float wself = __expf(leaky(gas[n] + adv));

    float2 acc;
    {
        float2 v = *reinterpret_cast<const float2*>(&h[n * HIDC + 2 * lane]);
        acc = make_float2(v.x * wself, v.y * wself);
    }
    float den = (lane == 0) ? wself : 0.f;

    for (int base = start; base < end; base += 32) {
        int i = base + lane;
        if (i < end) {
            int s = g_csr[i];
            s_sh[wid][lane] = s;
            float w = __expf(leaky(gas[s] + adv));
            w_sh[wid][lane] = w;
            den += w;
        }
        __syncwarp();
        int cnt = min(32, end - base);
        for (int k = 0; k < cnt; k++) {
            int s = s_sh[wid][k];
            float w = w_sh[wid][k];
            float2 v = *reinterpret_cast<const float2*>(&h[s * HIDC + 2 * lane]);
            acc.x = fmaf(v.x, w, acc.x);
            acc.y = fmaf(v.y, w, acc.y);
        }
        __syncwarp();
    }
    for (int o = 16; o > 0; o >>= 1)
        den += __shfl_xor_sync(0xffffffffu, den, o);
    float inv = 1.f / (den + 1e-16f);

    float2 b = *reinterpret_cast<const float2*>(&bias[2 * lane]);
    float vx = fmaf(acc.x, inv, b.x);
    float vy = fmaf(acc.y, inv, b.y);
    vx = vx > 0.f ? vx : (__expf(vx) - 1.f);
    vy = vy > 0.f ? vy : (__expf(vy) - 1.f);

    const int g = batch[n];
    atomicAdd(&g_pool[g * HIDC + 2 * lane], vx);
    atomicAdd(&g_pool[g * HIDC + 2 * lane + 1], vy);
    if (lane == 0) atomicAdd(&g_cnt[g], 1.f);
}

// ---------------- classifier --------------------------------------------------
__global__ void cls_kernel(const float* __restrict__ Wc, const float* __restrict__ bc,
                           float* __restrict__ out) {
    __shared__ float p[HIDC];
    int g = blockIdx.x;
    if (threadIdx.x < HIDC)
        p[threadIdx.x] = g_pool[g * HIDC + threadIdx.x] / fmaxf(g_cnt[g], 1.f);
    __syncthreads();
    for (int k = threadIdx.x; k < NCLS; k += blockDim.x) {
        float s = bc[k];
#pragma unroll
        for (int c = 0; c < HIDC; c++) s += p[c] * Wc[c * NCLS + k];
        out[g * NCLS + k] = s;
    }
}

// ---------------- launch ------------------------------------------------------
extern "C" void kernel_launch(void* const* d_in, const int* in_sizes, int n_in,
                              void* d_out, int out_size) {
    const float* x    = (const float*)d_in[0];
    const int*   ei   = (const int*)d_in[1];
    const int*   batch= (const int*)d_in[2];
    const float* W0   = (const float*)d_in[3];
    const float* as0  = (const float*)d_in[4];
    const float* ad0  = (const float*)d_in[5];
    const float* b0   = (const float*)d_in[6];
    const float* W1   = (const float*)d_in[7];
    const float* as1  = (const float*)d_in[8];
    const float* ad1  = (const float*)d_in[9];
    const float* b1   = (const float*)d_in[10];
    const float* W2   = (const float*)d_in[11];
    const float* as2  = (const float*)d_in[12];
    const float* ad2  = (const float*)d_in[13];
    const float* b2   = (const float*)d_in[14];
    const float* Wc   = (const float*)d_in[15];
    const float* bc   = (const float*)d_in[16];
    float* out = (float*)d_out;

    float *pA, *pB;
    cudaGetSymbolAddress((void**)&pA, g_bufA);
    cudaGetSymbolAddress((void**)&pB, g_bufB);
    float *pas0, *pad0, *pas1, *pad1, *pas2, *pad2;
    cudaGetSymbolAddress((void**)&pas0, g_as0);
    cudaGetSymbolAddress((void**)&pad0, g_ad0);
    cudaGetSymbolAddress((void**)&pas1, g_as1);
    cudaGetSymbolAddress((void**)&pad1, g_ad1);
    cudaGetSymbolAddress((void**)&pas2, g_as2);
    cudaGetSymbolAddress((void**)&pad2, g_ad2);

    zero_kernel<<<(NN + 255) / 256, 256>>>();
    hist_kernel<<<(EE + 255) / 256, 256>>>(ei);
    scan1_kernel<<<SCANB, 1024>>>();
    scan2_kernel<<<1, 64>>>();
    scan3_kernel<<<SCANB, 1024>>>();
    scatter_kernel<<<(EE + 255) / 256, 256>>>(ei);

    const int wgrid = (NN * 32 + 255) / 256;

    // layer 0: [50000,128] @ [128,256]
    dim3 g0((NN + 127) / 128, HC / 128);
    tgemm_kernel<128, 128, 16, 64, 32, HEADS><<<g0, 256>>>(
        x, W0, pA, NN, INC, HC, as0, ad0, pas0, pad0);
    agg4_kernel<<<wgrid, 256>>>(pA, b0, pB, pas0, pad0);

    // layer 1: [50000,256] @ [256,256]
    tgemm_kernel<128, 128, 16, 64, 32, HEADS><<<g0, 256>>>(
        pB, W1, pA, NN, HC, HC, as1, ad1, pas1, pad1);
    agg4_kernel<<<wgrid, 256>>>(pA, b1, pB, pas1, pad1);

    // layer 2: [50000,256] @ [256,64] (single head), fused pool
    dim3 g2((NN + 127) / 128, 1);
    tgemm_kernel<128, 64, 16, 32, 32, 1><<<g2, 256>>>(
        pB, W2, pA, NN, HC, HIDC, as2, ad2, pas2, pad2);
    agg1_kernel<<<wgrid, 256>>>(pA, b2, batch, pas2, pad2);

    cls_kernel<<<GG, 256>>>(Wc, bc, out);
}

// round 5
// speedup vs baseline: 2.2634x; 1.1852x over previous
#include <cuda_runtime.h>
#include <cuda_fp16.h>
#include <math.h>
#include <stdint.h>

#define NN    50000
#define EE    800000
#define INC   128
#define HEADS 4
#define HIDC  64
#define HC    256       // HEADS*HIDC
#define NCLS  200
#define GG    64
#define NEG   0.2f
#define SCANB 49        // ceil(NN/1024)

// ---------------- scratch (static device globals; no allocation) -------------
__device__ __align__(16) __half g_bufH[NN * HC];   // GEMM output h (fp16, gather path)
__device__ __align__(16) float  g_bufF[NN * HC];   // agg output (fp32, next GEMM input)
__device__ __align__(16) float g_as0[NN * HEADS];
__device__ __align__(16) float g_ad0[NN * HEADS];
__device__ __align__(16) float g_as1[NN * HEADS];
__device__ __align__(16) float g_ad1[NN * HEADS];
__device__ float g_as2[NN];
__device__ float g_ad2[NN];
__device__ int   g_deg[NN];
__device__ int   g_rowptr[NN + 1];
__device__ int   g_wp[NN];
__device__ int   g_csr[EE];
__device__ int   g_bsum[64];
__device__ float g_pool[GG * HIDC];
__device__ float g_cnt[GG];

__device__ __forceinline__ float leaky(float z) { return z > 0.f ? z : NEG * z; }

__device__ __forceinline__ uint32_t f2tf32(float f) {
    uint32_t u;
    asm("cvt.rna.tf32.f32 %0, %1;" : "=r"(u) : "f"(f));
    return u;
}

// ---------------- graph prep ------------------------------------------------
__global__ void zero_kernel() {
    int tid = blockIdx.x * blockDim.x + threadIdx.x;
    if (tid < NN) {
        g_deg[tid] = 0;
        const float4 z4 = make_float4(0.f, 0.f, 0.f, 0.f);
        *reinterpret_cast<float4*>(&g_as0[4 * tid]) = z4;
        *reinterpret_cast<float4*>(&g_ad0[4 * tid]) = z4;
        *reinterpret_cast<float4*>(&g_as1[4 * tid]) = z4;
        *reinterpret_cast<float4*>(&g_ad1[4 * tid]) = z4;
        g_as2[tid] = 0.f;
        g_ad2[tid] = 0.f;
    }
    if (tid < GG * HIDC) g_pool[tid] = 0.f;
    if (tid < GG) g_cnt[tid] = 0.f;
}

__global__ void hist_kernel(const int* __restrict__ ei) {
    int e = blockIdx.x * blockDim.x + threadIdx.x;
    if (e < EE) atomicAdd(&g_deg[ei[EE + e]], 1);
}

__global__ void scan1_kernel() {
    __shared__ int sh[1024];
    int t = threadIdx.x;
    int idx = blockIdx.x * 1024 + t;
    int v = (idx < NN) ? g_deg[idx] : 0;
    sh[t] = v;
    __syncthreads();
    for (int off = 1; off < 1024; off <<= 1) {
        int u = (t >= off) ? sh[t - off] : 0;
        __syncthreads();
        sh[t] += u;
        __syncthreads();
    }
    if (idx < NN) g_rowptr[idx] = sh[t] - v;
    if (t == 1023) g_bsum[blockIdx.x] = sh[1023];
}

__global__ void scan2_kernel() {
    __shared__ int sh[64];
    int t = threadIdx.x;
    int v = (t < SCANB) ? g_bsum[t] : 0;
    sh[t] = v;
    __syncthreads();
    for (int off = 1; off < 64; off <<= 1) {
        int u = (t >= off) ? sh[t - off] : 0;
        __syncthreads();
        sh[t] += u;
        __syncthreads();
    }
    g_bsum[t] = sh[t] - v;
}

__global__ void scan3_kernel() {
    int idx = blockIdx.x * 1024 + threadIdx.x;
    if (idx < NN) {
        int r = g_rowptr[idx] + g_bsum[blockIdx.x];
        g_rowptr[idx] = r;
        g_wp[idx] = r;
        if (idx == NN - 1) g_rowptr[NN] = r + g_deg[idx];
    }
}

__global__ void scatter_kernel(const int* __restrict__ ei) {
    int e = blockIdx.x * blockDim.x + threadIdx.x;
    if (e < EE) {
        int d = ei[EE + e];
        int p = atomicAdd(&g_wp[d], 1);
        g_csr[p] = ei[e];
    }
}

// ------- TF32 tensor-core GEMM + fused attention-logit epilogue --------------
// C (fp16) = A @ B; logits accumulated in fp32 from MMA accumulators.
template <int BM, int BN, int BK, int WM, int WN, int H>
__global__ __launch_bounds__(256) void tgemm_kernel(
        const float* __restrict__ A, const float* __restrict__ B,
        __half* __restrict__ C, int M, int K, int Nn,
        const float* __restrict__ a_s, const float* __restrict__ a_d,
        float* __restrict__ gas, float* __restrict__ gad) {
    constexpr int PAD = 8;
    __shared__ uint32_t As[2][BK][BM + PAD];
    __shared__ uint32_t Bs[2][BK][BN + PAD];
    constexpr int WARPS_N = BN / WN;
    constexpr int MT = WM / 16, NT = WN / 8;

    const int tid = threadIdx.x, wid = tid >> 5, lane = tid & 31;
    const int wm = (wid / WARPS_N) * WM, wn = (wid % WARPS_N) * WN;
    const int bm = blockIdx.x * BM, bn = blockIdx.y * BN;

    float acc[MT][NT][4] = {};

    constexpr int LA = (BM * BK) / (4 * 256);
    constexpr int LB = (BK * BN) / (4 * 256);
    float4 ra[LA], rb[LB];

    auto load = [&](int k0) {
#pragma unroll
        for (int i = 0; i < LA; i++) {
            int idx = i * 256 + tid;
            int r = idx / (BK / 4), c4 = idx % (BK / 4);
            int gr = bm + r;
            ra[i] = (gr < M) ? *reinterpret_cast<const float4*>(&A[gr * K + k0 + 4 * c4])
                             : make_float4(0.f, 0.f, 0.f, 0.f);
        }
#pragma unroll
        for (int i = 0; i < LB; i++) {
            int idx = i * 256 + tid;
            int r = idx / (BN / 4), c4 = idx % (BN / 4);
            rb[i] = *reinterpret_cast<const float4*>(&B[(k0 + r) * Nn + bn + 4 * c4]);
        }
    };
    auto store = [&](int buf) {
#pragma unroll
        for (int i = 0; i < LA; i++) {
            int idx = i * 256 + tid;
            int r = idx / (BK / 4), c4 = idx % (BK / 4);
            As[buf][4 * c4 + 0][r] = f2tf32(ra[i].x);
            As[buf][4 * c4 + 1][r] = f2tf32(ra[i].y);
            As[buf][4 * c4 + 2][r] = f2tf32(ra[i].z);
            As[buf][4 * c4 + 3][r] = f2tf32(ra[i].w);
        }
#pragma unroll
        for (int i = 0; i < LB; i++) {
            int idx = i * 256 + tid;
            int r = idx / (BN / 4), c4 = idx % (BN / 4);
            uint4 b4;
            b4.x = f2tf32(rb[i].x); b4.y = f2tf32(rb[i].y);
            b4.z = f2tf32(rb[i].z); b4.w = f2tf32(rb[i].w);
            *reinterpret_cast<uint4*>(&Bs[buf][r][4 * c4]) = b4;
        }
    };

    const int ntiles = K / BK;
    load(0);
    store(0);
    __syncthreads();
    int buf = 0;
    for (int t = 0; t < ntiles; t++) {
        if (t + 1 < ntiles) load((t + 1) * BK);
#pragma unroll
        for (int ks = 0; ks < BK / 8; ks++) {
            uint32_t af[MT][4], bf[NT][2];
            const int krow = ks * 8 + (lane & 3);
#pragma unroll
            for (int mt = 0; mt < MT; mt++) {
                int m0 = wm + mt * 16 + (lane >> 2);
                af[mt][0] = As[buf][krow][m0];
                af[mt][1] = As[buf][krow][m0 + 8];
                af[mt][2] = As[buf][krow + 4][m0];
                af[mt][3] = As[buf][krow + 4][m0 + 8];
            }
#pragma unroll
            for (int nt = 0; nt < NT; nt++) {
                int n0 = wn + nt * 8 + (lane >> 2);
                bf[nt][0] = Bs[buf][krow][n0];
                bf[nt][1] = Bs[buf][krow + 4][n0];
            }
#pragma unroll
            for (int mt = 0; mt < MT; mt++)
#pragma unroll
                for (int nt = 0; nt < NT; nt++)
                    asm volatile(
                        "mma.sync.aligned.m16n8k8.row.col.f32.tf32.tf32.f32 "
                        "{%0,%1,%2,%3},{%4,%5,%6,%7},{%8,%9},{%0,%1,%2,%3};"
                        : "+f"(acc[mt][nt][0]), "+f"(acc[mt][nt][1]),
                          "+f"(acc[mt][nt][2]), "+f"(acc[mt][nt][3])
                        : "r"(af[mt][0]), "r"(af[mt][1]), "r"(af[mt][2]), "r"(af[mt][3]),
                          "r"(bf[nt][0]), "r"(bf[nt][1]));
        }
        if (t + 1 < ntiles) {
            store(buf ^ 1);
            __syncthreads();
            buf ^= 1;
        }
    }

    float asr[NT][2], adr[NT][2];
#pragma unroll
    for (int nt = 0; nt < NT; nt++) {
#pragma unroll
        for (int j = 0; j < 2; j++) {
            int c = bn + wn + nt * 8 + 2 * (lane & 3) + j;
            asr[nt][j] = a_s[c];
            adr[nt][j] = a_d[c];
        }
    }
    const int head = (H == 1) ? 0 : ((bn + wn) >> 6);

#pragma unroll
    for (int mt = 0; mt < MT; mt++) {
#pragma unroll
        for (int half_ = 0; half_ < 2; half_++) {
            int row = bm + wm + mt * 16 + (lane >> 2) + half_ * 8;
            float ps = 0.f, pd = 0.f;
            if (row < M) {
#pragma unroll
                for (int nt = 0; nt < NT; nt++) {
                    int c0 = bn + wn + nt * 8 + 2 * (lane & 3);
                    float v0 = acc[mt][nt][half_ * 2 + 0];
                    float v1 = acc[mt][nt][half_ * 2 + 1];
                    *reinterpret_cast<__half2*>(&C[row * Nn + c0]) = __floats2half2_rn(v0, v1);
                    ps = fmaf(v0, asr[nt][0], ps); ps = fmaf(v1, asr[nt][1], ps);
                    pd = fmaf(v0, adr[nt][0], pd); pd = fmaf(v1, adr[nt][1], pd);
                }
            }
            ps += __shfl_xor_sync(0xffffffffu, ps, 1);
            ps += __shfl_xor_sync(0xffffffffu, ps, 2);
            pd += __shfl_xor_sync(0xffffffffu, pd, 1);
            pd += __shfl_xor_sync(0xffffffffu, pd, 2);
            if ((lane & 3) == 0 && row < M) {
                atomicAdd(&gas[row * H + head], ps);
                atomicAdd(&gad[row * H + head], pd);
            }
        }
    }
}

// -------- single-pass gather aggregation, H=4, fp16 gather, fp32 accum -------
// lane owns channels 8*lane .. 8*lane+7  (head = lane>>3); 1 LDG.128 per edge.
__global__ void agg4_kernel(const __half* __restrict__ h, const float* __restrict__ bias,
                            float* __restrict__ out,
                            const float* __restrict__ gas, const float* __restrict__ gad) {
    __shared__ float w_sh[8][32 * HEADS];
    __shared__ int   s_sh[8][32];
    const int wid = threadIdx.x >> 5, lane = threadIdx.x & 31;
    const int n = (blockIdx.x * blockDim.x + threadIdx.x) >> 5;
    if (n >= NN) return;

    const int start = g_rowptr[n], end = g_rowptr[n + 1];
    const float4 adv = *reinterpret_cast<const float4*>(&gad[n * 4]);
    const float4 asv = *reinterpret_cast<const float4*>(&gas[n * 4]);
    const float ad[4] = {adv.x, adv.y, adv.z, adv.w};

    float wself[4];
    wself[0] = __expf(leaky(asv.x + ad[0]));
    wself[1] = __expf(leaky(asv.y + ad[1]));
    wself[2] = __expf(leaky(asv.z + ad[2]));
    wself[3] = __expf(leaky(asv.w + ad[3]));

    const int hh = lane >> 3;          // head of this lane's 8 channels
    float acc[8];
    {
        uint4 raw = *reinterpret_cast<const uint4*>(&h[(size_t)n * HC + 8 * lane]);
        const __half2* hp = reinterpret_cast<const __half2*>(&raw);
        float w = wself[hh];
#pragma unroll
        for (int j = 0; j < 4; j++) {
            float2 f = __half22float2(hp[j]);
            acc[2 * j]     = f.x * w;
            acc[2 * j + 1] = f.y * w;
        }
    }
    float den[4];
#pragma unroll
    for (int q = 0; q < 4; q++) den[q] = (lane == 0) ? wself[q] : 0.f;

    for (int base = start; base < end; base += 32) {
        int i = base + lane;
        if (i < end) {
            int s = g_csr[i];
            s_sh[wid][lane] = s;
            float4 sa = *reinterpret_cast<const float4*>(&gas[s * 4]);
            float w0 = __expf(leaky(sa.x + ad[0]));
            float w1 = __expf(leaky(sa.y + ad[1]));
            float w2 = __expf(leaky(sa.z + ad[2]));
            float w3 = __expf(leaky(sa.w + ad[3]));
            w_sh[wid][lane * 4 + 0] = w0;
            w_sh[wid][lane * 4 + 1] = w1;
            w_sh[wid][lane * 4 + 2] = w2;
            w_sh[wid][lane * 4 + 3] = w3;
            den[0] += w0; den[1] += w1; den[2] += w2; den[3] += w3;
        }
        __syncwarp();
        int cnt = min(32, end - base);
        for (int k = 0; k < cnt; k++) {
            int s = s_sh[wid][k];
            float w = w_sh[wid][k * 4 + hh];
            uint4 raw = *reinterpret_cast<const uint4*>(&h[(size_t)s * HC + 8 * lane]);
            const __half2* hp = reinterpret_cast<const __half2*>(&raw);
#pragma unroll
            for (int j = 0; j < 4; j++) {
                float2 f = __half22float2(hp[j]);
                acc[2 * j]     = fmaf(f.x, w, acc[2 * j]);
                acc[2 * j + 1] = fmaf(f.y, w, acc[2 * j + 1]);
            }
        }
        __syncwarp();
    }
#pragma unroll
    for (int q = 0; q < 4; q++)
        for (int o = 16; o > 0; o >>= 1)
            den[q] += __shfl_xor_sync(0xffffffffu, den[q], o);
    const float inv = 1.f / (den[hh] + 1e-16f);

    float4 b0 = *reinterpret_cast<const float4*>(&bias[8 * lane]);
    float4 b1 = *reinterpret_cast<const float4*>(&bias[8 * lane + 4]);
    float o0[8];
    o0[0] = fmaf(acc[0], inv, b0.x); o0[1] = fmaf(acc[1], inv, b0.y);
    o0[2] = fmaf(acc[2], inv, b0.z); o0[3] = fmaf(acc[3], inv, b0.w);
    o0[4] = fmaf(acc[4], inv, b1.x); o0[5] = fmaf(acc[5], inv, b1.y);
    o0[6] = fmaf(acc[6], inv, b1.z); o0[7] = fmaf(acc[7], inv, b1.w);
#pragma unroll
    for (int j = 0; j < 8; j++) o0[j] = o0[j] > 0.f ? o0[j] : (__expf(o0[j]) - 1.f);
    *reinterpret_cast<float4*>(&out[(size_t)n * HC + 8 * lane])     =
        make_float4(o0[0], o0[1], o0[2], o0[3]);
    *reinterpret_cast<float4*>(&out[(size_t)n * HC + 8 * lane + 4]) =
        make_float4(o0[4], o0[5], o0[6], o0[7]);
}

// ---- single-pass aggregation, H=1 C=64, fp16 gather, fused mean-pool --------
__global__ void agg1_kernel(const __half* __restrict__ h, const float* __restrict__ bias,
                            const int* __restrict__ batch,
                            const float* __restrict__ gas, const float* __restrict__ gad) {
    __shared__ float w_sh[8][32];
    __shared__ int   s_sh[8][32];
    const int wid = threadIdx.x >> 5, lane = threadIdx.x & 31;
    const int n = (blockIdx.x * blockDim.x + threadIdx.x) >> 5;
    if (n >= NN) return;

    const int start = g_rowptr[n], end = g_rowptr[n + 1];
    const float adv = gad[n];
    const float wself = __expf(leaky(gas[n] + adv));

    float2 acc;
    {
        float2 v = __half22float2(*reinterpret_cast<const __half2*>(&h[(size_t)n * HIDC + 2 * lane]));
        acc = make_float2(v.x * wself, v.y * wself);
    }
    float den = (lane == 0) ? wself : 0.f;

    for (int base = start; base < end; base += 32) {
        int i = base + lane;
        if (i < end) {
            int s = g_csr[i];
            s_sh[wid][lane] = s;
            float w = __expf(leaky(gas[s] + adv));
            w_sh[wid][lane] = w;
            den += w;
        }
        __syncwarp();
        int cnt = min(32, end - base);
        for (int k = 0; k < cnt; k++) {
            int s = s_sh[wid][k];
            float w = w_sh[wid][k];
            float2 v = __half22float2(*reinterpret_cast<const __half2*>(&h[(size_t)s * HIDC + 2 * lane]));
            acc.x = fmaf(v.x, w, acc.x);
            acc.y = fmaf(v.y, w, acc.y);
        }
        __syncwarp();
    }
    for (int o = 16; o > 0; o >>= 1)
        den += __shfl_xor_sync(0xffffffffu, den, o);
    float inv = 1.f / (den + 1e-16f);

    float2 b = *reinterpret_cast<const float2*>(&bias[2 * lane]);
    float vx = fmaf(acc.x, inv, b.x);
    float vy = fmaf(acc.y, inv, b.y);
    vx = vx > 0.f ? vx : (__expf(vx) - 1.f);
    vy = vy > 0.f ? vy : (__expf(vy) - 1.f);

    const int g = batch[n];
    atomicAdd(&g_pool[g * HIDC + 2 * lane], vx);
    atomicAdd(&g_pool[g * HIDC + 2 * lane + 1], vy);
    if (lane == 0) atomicAdd(&g_cnt[g], 1.f);
}

// ---------------- classifier --------------------------------------------------
__global__ void cls_kernel(const float* __restrict__ Wc, const float* __restrict__ bc,
                           float* __restrict__ out) {
    __shared__ float p[HIDC];
    int g = blockIdx.x;
    if (threadIdx.x < HIDC)
        p[threadIdx.x] = g_pool[g * HIDC + threadIdx.x] / fmaxf(g_cnt[g], 1.f);
    __syncthreads();
    for (int k = threadIdx.x; k < NCLS; k += blockDim.x) {
        float s = bc[k];
#pragma unroll
        for (int c = 0; c < HIDC; c++) s += p[c] * Wc[c * NCLS + k];
        out[g * NCLS + k] = s;
    }
}

// ---------------- launch ------------------------------------------------------
extern "C" void kernel_launch(void* const* d_in, const int* in_sizes, int n_in,
                              void* d_out, int out_size) {
    const float* x    = (const float*)d_in[0];
    const int*   ei   = (const int*)d_in[1];
    const int*   batch= (const int*)d_in[2];
    const float* W0   = (const float*)d_in[3];
    const float* as0  = (const float*)d_in[4];
    const float* ad0  = (const float*)d_in[5];
    const float* b0   = (const float*)d_in[6];
    const float* W1   = (const float*)d_in[7];
    const float* as1  = (const float*)d_in[8];
    const float* ad1  = (const float*)d_in[9];
    const float* b1   = (const float*)d_in[10];
    const float* W2   = (const float*)d_in[11];
    const float* as2  = (const float*)d_in[12];
    const float* ad2  = (const float*)d_in[13];
    const float* b2   = (const float*)d_in[14];
    const float* Wc   = (const float*)d_in[15];
    const float* bc   = (const float*)d_in[16];
    float* out = (float*)d_out;

    __half* pH;
    float* pF;
    cudaGetSymbolAddress((void**)&pH, g_bufH);
    cudaGetSymbolAddress((void**)&pF, g_bufF);
    float *pas0, *pad0, *pas1, *pad1, *pas2, *pad2;
    cudaGetSymbolAddress((void**)&pas0, g_as0);
    cudaGetSymbolAddress((void**)&pad0, g_ad0);
    cudaGetSymbolAddress((void**)&pas1, g_as1);
    cudaGetSymbolAddress((void**)&pad1, g_ad1);
    cudaGetSymbolAddress((void**)&pas2, g_as2);
    cudaGetSymbolAddress((void**)&pad2, g_ad2);

    zero_kernel<<<(NN + 255) / 256, 256>>>();
    hist_kernel<<<(EE + 255) / 256, 256>>>(ei);
    scan1_kernel<<<SCANB, 1024>>>();
    scan2_kernel<<<1, 64>>>();
    scan3_kernel<<<SCANB, 1024>>>();
    scatter_kernel<<<(EE + 255) / 256, 256>>>(ei);

    const int wgrid = (NN * 32 + 255) / 256;

    // layer 0: [50000,128] @ [128,256]
    dim3 g0((NN + 127) / 128, HC / 128);
    tgemm_kernel<128, 128, 16, 64, 32, HEADS><<<g0, 256>>>(
        x, W0, pH, NN, INC, HC, as0, ad0, pas0, pad0);
    agg4_kernel<<<wgrid, 256>>>(pH, b0, pF, pas0, pad0);

    // layer 1: [50000,256] @ [256,256]
    tgemm_kernel<128, 128, 16, 64, 32, HEADS><<<g0, 256>>>(
        pF, W1, pH, NN, HC, HC, as1, ad1, pas1, pad1);
    agg4_kernel<<<wgrid, 256>>>(pH, b1, pF, pas1, pad1);

    // layer 2: [50000,256] @ [256,64] (single head), fused pool
    dim3 g2((NN + 127) / 128, 1);
    tgemm_kernel<128, 64, 16, 32, 32, 1><<<g2, 256>>>(
        pF, W2, pH, NN, HC, HIDC, as2, ad2, pas2, pad2);
    agg1_kernel<<<wgrid, 256>>>(pH, b2, batch, pas2, pad2);

    cls_kernel<<<GG, 256>>>(Wc, bc, out);
}

// round 6
// speedup vs baseline: 2.6484x; 1.1701x over previous
#include <cuda_runtime.h>
#include <cuda_fp16.h>
#include <math.h>
#include <stdint.h>

#define NN    50000
#define EE    800000
#define INC   128
#define HEADS 4
#define HIDC  64
#define HC    256       // HEADS*HIDC
#define NCLS  200
#define GG    64
#define NEG   0.2f
#define SCANB 49        // ceil(NN/1024)

// ---------------- scratch (static device globals; no allocation) -------------
__device__ __align__(16) __half g_bufH[NN * HC];   // GEMM output h (fp16, gather path)
__device__ __align__(16) __half g_bufG[NN * HC];   // agg output (fp16, next GEMM input)
__device__ __align__(16) __half g_w0h[INC * HC];
__device__ __align__(16) __half g_w1h[HC * HC];
__device__ __align__(16) __half g_w2h[HC * HIDC];
__device__ __align__(16) float g_as0[NN * HEADS];
__device__ __align__(16) float g_ad0[NN * HEADS];
__device__ __align__(16) float g_as1[NN * HEADS];
__device__ __align__(16) float g_ad1[NN * HEADS];
__device__ float g_as2[NN];
__device__ float g_ad2[NN];
__device__ int   g_deg[NN];
__device__ int   g_rowptr[NN + 1];
__device__ int   g_wp[NN];
__device__ int   g_csr[EE];
__device__ int   g_bsum[64];
__device__ float g_pool[GG * HIDC];
__device__ float g_cnt[GG];

__device__ __forceinline__ float leaky(float z) { return z > 0.f ? z : NEG * z; }
__device__ __forceinline__ uint32_t h2bits(__half2 h) { return *reinterpret_cast<uint32_t*>(&h); }

// ---------------- weight fp16 pre-convert ------------------------------------
// W0: 8192 float4, W1: 16384, W2: 4096  => 28672 total, 112 blocks x 256
__global__ void wconv_kernel(const float* __restrict__ W0, const float* __restrict__ W1,
                             const float* __restrict__ W2) {
    int i = blockIdx.x * 256 + threadIdx.x;
    const float4* src;
    __half* dst;
    int j;
    if (i < 8192)       { src = (const float4*)W0; dst = g_w0h; j = i; }
    else if (i < 24576) { src = (const float4*)W1; dst = g_w1h; j = i - 8192; }
    else if (i < 28672) { src = (const float4*)W2; dst = g_w2h; j = i - 24576; }
    else return;
    float4 v = src[j];
    __half2 a = __floats2half2_rn(v.x, v.y);
    __half2 b = __floats2half2_rn(v.z, v.w);
    *reinterpret_cast<uint2*>(&dst[4 * j]) = make_uint2(h2bits(a), h2bits(b));
}

// ---------------- graph prep ------------------------------------------------
__global__ void zero_kernel() {
    int tid = blockIdx.x * blockDim.x + threadIdx.x;
    if (tid < NN) {
        g_deg[tid] = 0;
        const float4 z4 = make_float4(0.f, 0.f, 0.f, 0.f);
        *reinterpret_cast<float4*>(&g_as0[4 * tid]) = z4;
        *reinterpret_cast<float4*>(&g_ad0[4 * tid]) = z4;
        *reinterpret_cast<float4*>(&g_as1[4 * tid]) = z4;
        *reinterpret_cast<float4*>(&g_ad1[4 * tid]) = z4;
        g_as2[tid] = 0.f;
        g_ad2[tid] = 0.f;
    }
    if (tid < GG * HIDC) g_pool[tid] = 0.f;
    if (tid < GG) g_cnt[tid] = 0.f;
}

__global__ void hist_kernel(const int* __restrict__ ei) {
    int e = blockIdx.x * blockDim.x + threadIdx.x;
    if (e < EE) atomicAdd(&g_deg[ei[EE + e]], 1);
}

__global__ void scan1_kernel() {
    __shared__ int sh[1024];
    int t = threadIdx.x;
    int idx = blockIdx.x * 1024 + t;
    int v = (idx < NN) ? g_deg[idx] : 0;
    sh[t] = v;
    __syncthreads();
    for (int off = 1; off < 1024; off <<= 1) {
        int u = (t >= off) ? sh[t - off] : 0;
        __syncthreads();
        sh[t] += u;
        __syncthreads();
    }
    if (idx < NN) g_rowptr[idx] = sh[t] - v;
    if (t == 1023) g_bsum[blockIdx.x] = sh[1023];
}

__global__ void scan2_kernel() {
    __shared__ int sh[64];
    int t = threadIdx.x;
    int v = (t < SCANB) ? g_bsum[t] : 0;
    sh[t] = v;
    __syncthreads();
    for (int off = 1; off < 64; off <<= 1) {
        int u = (t >= off) ? sh[t - off] : 0;
        __syncthreads();
        sh[t] += u;
        __syncthreads();
    }
    g_bsum[t] = sh[t] - v;
}

__global__ void scan3_kernel() {
    int idx = blockIdx.x * 1024 + threadIdx.x;
    if (idx < NN) {
        int r = g_rowptr[idx] + g_bsum[blockIdx.x];
        g_rowptr[idx] = r;
        g_wp[idx] = r;
        if (idx == NN - 1) g_rowptr[NN] = r + g_deg[idx];
    }
}

__global__ void scatter_kernel(const int* __restrict__ ei) {
    int e = blockIdx.x * blockDim.x + threadIdx.x;
    if (e < EE) {
        int d = ei[EE + e];
        int p = atomicAdd(&g_wp[d], 1);
        g_csr[p] = ei[e];
    }
}

// ------- fp16 tensor-core GEMM (m16n8k16, fp32 accum) + fused logits ---------
// C (fp16) = A @ B;  gas/gad accumulated in fp32 from MMA accumulators.
// AF32: A source is fp32 (layer 0, x); else fp16.
template <int BM, int BN, int BK, int WM, int WN, int H, bool AF32>
__global__ __launch_bounds__(256) void hgemm_kernel(
        const void* __restrict__ Aptr, const __half* __restrict__ Bh,
        __half* __restrict__ C, int M, int K, int Nn,
        const float* __restrict__ a_s, const float* __restrict__ a_d,
        float* __restrict__ gas, float* __restrict__ gad) {
    constexpr int PAD = 8;
    constexpr int K2 = BK / 2;
    __shared__ uint32_t As2[2][K2][BM + PAD];   // [k/2][m] half2
    __shared__ uint32_t Bs2[2][K2][BN + PAD];   // [k/2][n] half2
    constexpr int WARPS_N = BN / WN;
    constexpr int MT = WM / 16, NT = WN / 8;
    constexpr int CB = (BK / 2) * (BN / 8);     // B super-elements per tile

    const int tid = threadIdx.x, lane = tid & 31;
    const int wid = tid >> 5;
    const int wm = (wid / WARPS_N) * WM, wn = (wid % WARPS_N) * WN;
    const int bm = blockIdx.x * BM, bn = blockIdx.y * BN;

    float acc[MT][NT][4] = {};

    // A staging regs
    float4 raf[AF32 ? 4 : 1];
    uint4  rah[AF32 ? 1 : 2];
    // B staging
    uint4 rbl, rbh;
    const int bk2 = tid / (BN / 8), bc8 = tid % (BN / 8);
    const bool bvalid = tid < CB;

    auto load = [&](int k0) {
        if constexpr (AF32) {
            const float* A = (const float*)Aptr;
#pragma unroll
            for (int i = 0; i < 4; i++) {
                int idx = i * 256 + tid;
                int r = idx >> 3, c4 = idx & 7;
                int gr = bm + r;
                raf[i] = (gr < M) ? *reinterpret_cast<const float4*>(&A[gr * K + k0 + 4 * c4])
                                  : make_float4(0.f, 0.f, 0.f, 0.f);
            }
        } else {
            const __half* A = (const __half*)Aptr;
#pragma unroll
            for (int i = 0; i < 2; i++) {
                int idx = i * 256 + tid;
                int r = idx >> 2, c8 = idx & 3;
                int gr = bm + r;
                rah[i] = (gr < M) ? *reinterpret_cast<const uint4*>(&A[(size_t)gr * K + k0 + 8 * c8])
                                  : make_uint4(0u, 0u, 0u, 0u);
            }
        }
        if (bvalid) {
            rbl = *reinterpret_cast<const uint4*>(&Bh[(size_t)(k0 + 2 * bk2) * Nn + bn + 8 * bc8]);
            rbh = *reinterpret_cast<const uint4*>(&Bh[(size_t)(k0 + 2 * bk2 + 1) * Nn + bn + 8 * bc8]);
        }
    };
    auto store = [&](int buf) {
        if constexpr (AF32) {
#pragma unroll
            for (int i = 0; i < 4; i++) {
                int idx = i * 256 + tid;
                int r = idx >> 3, c4 = idx & 7;
                As2[buf][2 * c4][r]     = h2bits(__floats2half2_rn(raf[i].x, raf[i].y));
                As2[buf][2 * c4 + 1][r] = h2bits(__floats2half2_rn(raf[i].z, raf[i].w));
            }
        } else {
#pragma unroll
            for (int i = 0; i < 2; i++) {
                int idx = i * 256 + tid;
                int r = idx >> 2, c8 = idx & 3;
                const uint32_t* p = reinterpret_cast<const uint32_t*>(&rah[i]);
#pragma unroll
                for (int j = 0; j < 4; j++) As2[buf][4 * c8 + j][r] = p[j];
            }
        }
        if (bvalid) {
            const __half* lo = reinterpret_cast<const __half*>(&rbl);
            const __half* hi = reinterpret_cast<const __half*>(&rbh);
            uint32_t tmp[8];
#pragma unroll
            for (int j = 0; j < 8; j++) tmp[j] = h2bits(__halves2half2(lo[j], hi[j]));
            *reinterpret_cast<uint4*>(&Bs2[buf][bk2][8 * bc8])     = *reinterpret_cast<uint4*>(&tmp[0]);
            *reinterpret_cast<uint4*>(&Bs2[buf][bk2][8 * bc8 + 4]) = *reinterpret_cast<uint4*>(&tmp[4]);
        }
    };

    const int ntiles = K / BK;
    load(0);
    store(0);
    __syncthreads();
    int buf = 0;
    const int t4 = lane & 3, g8 = lane >> 2;
    for (int t = 0; t < ntiles; t++) {
        if (t + 1 < ntiles) load((t + 1) * BK);
#pragma unroll
        for (int ks = 0; ks < BK / 16; ks++) {
            const int base = ks * 8;
            uint32_t af[MT][4], bf[NT][2];
#pragma unroll
            for (int mt = 0; mt < MT; mt++) {
                int m0 = wm + mt * 16 + g8;
                af[mt][0] = As2[buf][base + t4][m0];
                af[mt][1] = As2[buf][base + t4][m0 + 8];
                af[mt][2] = As2[buf][base + t4 + 4][m0];
                af[mt][3] = As2[buf][base + t4 + 4][m0 + 8];
            }
#pragma unroll
            for (int nt = 0; nt < NT; nt++) {
                int n0 = wn + nt * 8 + g8;
                bf[nt][0] = Bs2[buf][base + t4][n0];
                bf[nt][1] = Bs2[buf][base + t4 + 4][n0];
            }
#pragma unroll
            for (int mt = 0; mt < MT; mt++)
#pragma unroll
                for (int nt = 0; nt < NT; nt++)
                    asm volatile(
                        "mma.sync.aligned.m16n8k16.row.col.f32.f16.f16.f32 "
                        "{%0,%1,%2,%3},{%4,%5,%6,%7},{%8,%9},{%0,%1,%2,%3};"
                        : "+f"(acc[mt][nt][0]), "+f"(acc[mt][nt][1]),
                          "+f"(acc[mt][nt][2]), "+f"(acc[mt][nt][3])
                        : "r"(af[mt][0]), "r"(af[mt][1]), "r"(af[mt][2]), "r"(af[mt][3]),
                          "r"(bf[nt][0]), "r"(bf[nt][1]));
        }
        if (t + 1 < ntiles) {
            store(buf ^ 1);
            __syncthreads();
            buf ^= 1;
        }
    }

    float asr[NT][2], adr[NT][2];
#pragma unroll
    for (int nt = 0; nt < NT; nt++) {
#pragma unroll
        for (int j = 0; j < 2; j++) {
            int c = bn + wn + nt * 8 + 2 * t4 + j;
            asr[nt][j] = a_s[c];
            adr[nt][j] = a_d[c];
        }
    }
    const int head = (H == 1) ? 0 : ((bn + wn) >> 6);

#pragma unroll
    for (int mt = 0; mt < MT; mt++) {
#pragma unroll
        for (int half_ = 0; half_ < 2; half_++) {
            int row = bm + wm + mt * 16 + g8 + half_ * 8;
            float ps = 0.f, pd = 0.f;
            if (row < M) {
#pragma unroll
                for (int nt = 0; nt < NT; nt++) {
                    int c0 = bn + wn + nt * 8 + 2 * t4;
                    float v0 = acc[mt][nt][half_ * 2 + 0];
                    float v1 = acc[mt][nt][half_ * 2 + 1];
                    *reinterpret_cast<__half2*>(&C[(size_t)row * Nn + c0]) = __floats2half2_rn(v0, v1);
                    ps = fmaf(v0, asr[nt][0], ps); ps = fmaf(v1, asr[nt][1], ps);
                    pd = fmaf(v0, adr[nt][0], pd); pd = fmaf(v1, adr[nt][1], pd);
                }
            }
            ps += __shfl_xor_sync(0xffffffffu, ps, 1);
            ps += __shfl_xor_sync(0xffffffffu, ps, 2);
            pd += __shfl_xor_sync(0xffffffffu, pd, 1);
            pd += __shfl_xor_sync(0xffffffffu, pd, 2);
            if (t4 == 0 && row < M) {
                atomicAdd(&gas[row * H + head], ps);
                atomicAdd(&gad[row * H + head], pd);
            }
        }
    }
}

// -------- single-pass gather aggregation, H=4, fp16 gather, fp16 out ---------
__global__ void agg4_kernel(const __half* __restrict__ h, const float* __restrict__ bias,
                            __half* __restrict__ out,
                            const float* __restrict__ gas, const float* __restrict__ gad) {
    __shared__ float w_sh[8][32 * HEADS];
    __shared__ int   s_sh[8][32];
    const int wid = threadIdx.x >> 5, lane = threadIdx.x & 31;
    const int n = (blockIdx.x * blockDim.x + threadIdx.x) >> 5;
    if (n >= NN) return;

    const int start = g_rowptr[n], end = g_rowptr[n + 1];
    const float4 adv = *reinterpret_cast<const float4*>(&gad[n * 4]);
    const float4 asv = *reinterpret_cast<const float4*>(&gas[n * 4]);
    const float ad[4] = {adv.x, adv.y, adv.z, adv.w};

    float wself[4];
    wself[0] = __expf(leaky(asv.x + ad[0]));
    wself[1] = __expf(leaky(asv.y + ad[1]));
    wself[2] = __expf(leaky(asv.z + ad[2]));
    wself[3] = __expf(leaky(asv.w + ad[3]));

    const int hh = lane >> 3;
    float acc[8];
    {
        uint4 raw = *reinterpret_cast<const uint4*>(&h[(size_t)n * HC + 8 * lane]);
        const __half2* hp = reinterpret_cast<const __half2*>(&raw);
        float w = wself[hh];
#pragma unroll
        for (int j = 0; j < 4; j++) {
            float2 f = __half22float2(hp[j]);
            acc[2 * j]     = f.x * w;
            acc[2 * j + 1] = f.y * w;
        }
    }
    float den[4];
#pragma unroll
    for (int q = 0; q < 4; q++) den[q] = (lane == 0) ? wself[q] : 0.f;

    for (int base = start; base < end; base += 32) {
        int i = base + lane;
        if (i < end) {
            int s = g_csr[i];
            s_sh[wid][lane] = s;
            float4 sa = *reinterpret_cast<const float4*>(&gas[s * 4]);
            float w0 = __expf(leaky(sa.x + ad[0]));
            float w1 = __expf(leaky(sa.y + ad[1]));
            float w2 = __expf(leaky(sa.z + ad[2]));
            float w3 = __expf(leaky(sa.w + ad[3]));
            w_sh[wid][lane * 4 + 0] = w0;
            w_sh[wid][lane * 4 + 1] = w1;
            w_sh[wid][lane * 4 + 2] = w2;
            w_sh[wid][lane * 4 + 3] = w3;
            den[0] += w0; den[1] += w1; den[2] += w2; den[3] += w3;
        }
        __syncwarp();
        int cnt = min(32, end - base);
        for (int k = 0; k < cnt; k++) {
            int s = s_sh[wid][k];
            float w = w_sh[wid][k * 4 + hh];
            uint4 raw = *reinterpret_cast<const uint4*>(&h[(size_t)s * HC + 8 * lane]);
            const __half2* hp = reinterpret_cast<const __half2*>(&raw);
#pragma unroll
            for (int j = 0; j < 4; j++) {
                float2 f = __half22float2(hp[j]);
                acc[2 * j]     = fmaf(f.x, w, acc[2 * j]);
                acc[2 * j + 1] = fmaf(f.y, w, acc[2 * j + 1]);
            }
        }
        __syncwarp();
    }
#pragma unroll
    for (int q = 0; q < 4; q++)
        for (int o = 16; o > 0; o >>= 1)
            den[q] += __shfl_xor_sync(0xffffffffu, den[q], o);
    const float inv = 1.f / (den[hh] + 1e-16f);

    float4 b0 = *reinterpret_cast<const float4*>(&bias[8 * lane]);
    float4 b1 = *reinterpret_cast<const float4*>(&bias[8 * lane + 4]);
    float o0[8];
    o0[0] = fmaf(acc[0], inv, b0.x); o0[1] = fmaf(acc[1], inv, b0.y);
    o0[2] = fmaf(acc[2], inv, b0.z); o0[3] = fmaf(acc[3], inv, b0.w);
    o0[4] = fmaf(acc[4], inv, b1.x); o0[5] = fmaf(acc[5], inv, b1.y);
    o0[6] = fmaf(acc[6], inv, b1.z); o0[7] = fmaf(acc[7], inv, b1.w);
#pragma unroll
    for (int j = 0; j < 8; j++) o0[j] = o0[j] > 0.f ? o0[j] : (__expf(o0[j]) - 1.f);
    uint4 ov;
    __half2* op = reinterpret_cast<__half2*>(&ov);
    op[0] = __floats2half2_rn(o0[0], o0[1]);
    op[1] = __floats2half2_rn(o0[2], o0[3]);
    op[2] = __floats2half2_rn(o0[4], o0[5]);
    op[3] = __floats2half2_rn(o0[6], o0[7]);
    *reinterpret_cast<uint4*>(&out[(size_t)n * HC + 8 * lane]) = ov;
}

// ---- single-pass aggregation, H=1 C=64, fp16 gather, fused mean-pool --------
__global__ void agg1_kernel(const __half* __restrict__ h, const float* __restrict__ bias,
                            const int* __restrict__ batch,
                            const float* __restrict__ gas, const float* __restrict__ gad) {
    __shared__ float w_sh[8][32];
    __shared__ int   s_sh[8][32];
    const int wid = threadIdx.x >> 5, lane = threadIdx.x & 31;
    const int n = (blockIdx.x * blockDim.x + threadIdx.x) >> 5;
    if (n >= NN) return;

    const int start = g_rowptr[n], end = g_rowptr[n + 1];
    const float adv = gad[n];
    const float wself = __expf(leaky(gas[n] + adv));

    float2 acc;
    {
        float2 v = __half22float2(*reinterpret_cast<const __half2*>(&h[(size_t)n * HIDC + 2 * lane]));
        acc = make_float2(v.x * wself, v.y * wself);
    }
    float den = (lane == 0) ? wself : 0.f;

    for (int base = start; base < end; base += 32) {
        int i = base + lane;
        if (i < end) {
            int s = g_csr[i];
            s_sh[wid][lane] = s;
            float w = __expf(leaky(gas[s] + adv));
            w_sh[wid][lane] = w;
            den += w;
        }
        __syncwarp();
        int cnt = min(32, end - base);
        for (int k = 0; k < cnt; k++) {
            int s = s_sh[wid][k];
            float w = w_sh[wid][k];
            float2 v = __half22float2(*reinterpret_cast<const __half2*>(&h[(size_t)s * HIDC + 2 * lane]));
            acc.x = fmaf(v.x, w, acc.x);
            acc.y = fmaf(v.y, w, acc.y);
        }
        __syncwarp();
    }
    for (int o = 16; o > 0; o >>= 1)
        den += __shfl_xor_sync(0xffffffffu, den, o);
    float inv = 1.f / (den + 1e-16f);

    float2 b = *reinterpret_cast<const float2*>(&bias[2 * lane]);
    float vx = fmaf(acc.x, inv, b.x);
    float vy = fmaf(acc.y, inv, b.y);
    vx = vx > 0.f ? vx : (__expf(vx) - 1.f);
    vy = vy > 0.f ? vy : (__expf(vy) - 1.f);

    const int g = batch[n];
    atomicAdd(&g_pool[g * HIDC + 2 * lane], vx);
    atomicAdd(&g_pool[g * HIDC + 2 * lane + 1], vy);
    if (lane == 0) atomicAdd(&g_cnt[g], 1.f);
}

// ---------------- classifier --------------------------------------------------
__global__ void cls_kernel(const float* __restrict__ Wc, const float* __restrict__ bc,
                           float* __restrict__ out) {
    __shared__ float p[HIDC];
    int g = blockIdx.x;
    if (threadIdx.x < HIDC)
        p[threadIdx.x] = g_pool[g * HIDC + threadIdx.x] / fmaxf(g_cnt[g], 1.f);
    __syncthreads();
    for (int k = threadIdx.x; k < NCLS; k += blockDim.x) {
        float s = bc[k];
#pragma unroll
        for (int c = 0; c < HIDC; c++) s += p[c] * Wc[c * NCLS + k];
        out[g * NCLS + k] = s;
    }
}

// ---------------- launch ------------------------------------------------------
extern "C" void kernel_launch(void* const* d_in, const int* in_sizes, int n_in,
                              void* d_out, int out_size) {
    const float* x    = (const float*)d_in[0];
    const int*   ei   = (const int*)d_in[1];
    const int*   batch= (const int*)d_in[2];
    const float* W0   = (const float*)d_in[3];
    const float* as0  = (const float*)d_in[4];
    const float* ad0  = (const float*)d_in[5];
    const float* b0   = (const float*)d_in[6];
    const float* W1   = (const float*)d_in[7];
    const float* as1  = (const float*)d_in[8];
    const float* ad1  = (const float*)d_in[9];
    const float* b1   = (const float*)d_in[10];
    const float* W2   = (const float*)d_in[11];
    const float* as2  = (const float*)d_in[12];
    const float* ad2  = (const float*)d_in[13];
    const float* b2   = (const float*)d_in[14];
    const float* Wc   = (const float*)d_in[15];
    const float* bc   = (const float*)d_in[16];
    float* out = (float*)d_out;

    __half *pH, *pG, *pw0, *pw1, *pw2;
    cudaGetSymbolAddress((void**)&pH, g_bufH);
    cudaGetSymbolAddress((void**)&pG, g_bufG);
    cudaGetSymbolAddress((void**)&pw0, g_w0h);
    cudaGetSymbolAddress((void**)&pw1, g_w1h);
    cudaGetSymbolAddress((void**)&pw2, g_w2h);
    float *pas0, *pad0, *pas1, *pad1, *pas2, *pad2;
    cudaGetSymbolAddress((void**)&pas0, g_as0);
    cudaGetSymbolAddress((void**)&pad0, g_ad0);
    cudaGetSymbolAddress((void**)&pas1, g_as1);
    cudaGetSymbolAddress((void**)&pad1, g_ad1);
    cudaGetSymbolAddress((void**)&pas2, g_as2);
    cudaGetSymbolAddress((void**)&pad2, g_ad2);

    wconv_kernel<<<112, 256>>>(W0, W1, W2);
    zero_kernel<<<(NN + 255) / 256, 256>>>();
    hist_kernel<<<(EE + 255) / 256, 256>>>(ei);
    scan1_kernel<<<SCANB, 1024>>>();
    scan2_kernel<<<1, 64>>>();
    scan3_kernel<<<SCANB, 1024>>>();
    scatter_kernel<<<(EE + 255) / 256, 256>>>(ei);

    const int wgrid = (NN * 32 + 255) / 256;

    // layer 0: [50000,128] @ [128,256]  (A fp32)
    dim3 g0((NN + 127) / 128, HC / 128);
    hgemm_kernel<128, 128, 32, 64, 32, HEADS, true><<<g0, 256>>>(
        x, pw0, pH, NN, INC, HC, as0, ad0, pas0, pad0);
    agg4_kernel<<<wgrid, 256>>>(pH, b0, pG, pas0, pad0);

    // layer 1: [50000,256] @ [256,256]  (A fp16)
    hgemm_kernel<128, 128, 32, 64, 32, HEADS, false><<<g0, 256>>>(
        pG, pw1, pH, NN, HC, HC, as1, ad1, pas1, pad1);
    agg4_kernel<<<wgrid, 256>>>(pH, b1, pG, pas1, pad1);

    // layer 2: [50000,256] @ [256,64] (single head), fused pool
    dim3 g2((NN + 127) / 128, 1);
    hgemm_kernel<128, 64, 32, 32, 32, 1, false><<<g2, 256>>>(
        pG, pw2, pH, NN, HC, HIDC, as2, ad2, pas2, pad2);
    agg1_kernel<<<wgrid, 256>>>(pH, b2, batch, pas2, pad2);

    cls_kernel<<<GG, 256>>>(Wc, bc, out);
}

// round 8
// speedup vs baseline: 2.7175x; 1.0261x over previous
#include <cuda_runtime.h>
#include <cuda_fp16.h>
#include <math.h>
#include <stdint.h>

#define NN    50000
#define EE    800000
#define INC   128
#define HEADS 4
#define HIDC  64
#define HC    256       // HEADS*HIDC
#define NCLS  200
#define GG    64
#define NEG   0.2f
#define SCANB 49        // ceil(NN/1024)

// ---------------- scratch (static device globals; no allocation) -------------
__device__ __align__(16) __half g_bufH[NN * HC];   // GEMM output h (fp16, gather path)
__device__ __align__(16) __half g_bufG[NN * HC];   // agg output (fp16, next GEMM input)
__device__ __align__(16) __half g_w0h[INC * HC];
__device__ __align__(16) __half g_w1h[HC * HC];
__device__ __align__(16) __half g_w2h[HC * HIDC];
__device__ __align__(16) float g_as0[NN * HEADS];
__device__ __align__(16) float g_ad0[NN * HEADS];
__device__ __align__(16) float g_as1[NN * HEADS];
__device__ __align__(16) float g_ad1[NN * HEADS];
__device__ float g_as2[NN];
__device__ float g_ad2[NN];
__device__ int   g_deg[NN];
__device__ int   g_rowptr[NN + 1];
__device__ int   g_wp[NN];
__device__ int   g_csr[EE];
__device__ int   g_bsum[64];
__device__ float g_pool[GG * HIDC];
__device__ float g_cnt[GG];

__device__ __forceinline__ float leaky(float z) { return z > 0.f ? z : NEG * z; }
__device__ __forceinline__ uint32_t h2bits(__half2 h) { return *reinterpret_cast<uint32_t*>(&h); }

// ------- main-stream prep: weight fp16 convert + zero logits/pool ------------
__global__ void prep0_kernel(const float* __restrict__ W0, const float* __restrict__ W1,
                             const float* __restrict__ W2) {
    int i = blockIdx.x * 256 + threadIdx.x;
    if (i < 28672) {
        const float4* src;
        __half* dst;
        int j;
        if (i < 8192)       { src = (const float4*)W0; dst = g_w0h; j = i; }
        else if (i < 24576) { src = (const float4*)W1; dst = g_w1h; j = i - 8192; }
        else                { src = (const float4*)W2; dst = g_w2h; j = i - 24576; }
        float4 v = src[j];
        __half2 a = __floats2half2_rn(v.x, v.y);
        __half2 b = __floats2half2_rn(v.z, v.w);
        *reinterpret_cast<uint2*>(&dst[4 * j]) = make_uint2(h2bits(a), h2bits(b));
    }
    if (i < NN) {
        const float4 z4 = make_float4(0.f, 0.f, 0.f, 0.f);
        *reinterpret_cast<float4*>(&g_as0[4 * i]) = z4;
        *reinterpret_cast<float4*>(&g_ad0[4 * i]) = z4;
        *reinterpret_cast<float4*>(&g_as1[4 * i]) = z4;
        *reinterpret_cast<float4*>(&g_ad1[4 * i]) = z4;
        g_as2[i] = 0.f;
        g_ad2[i] = 0.f;
    }
    if (i < GG * HIDC) g_pool[i] = 0.f;
    if (i < GG) g_cnt[i] = 0.f;
}

// ---------------- graph prep (side stream) -----------------------------------
__global__ void zdeg_kernel() {
    int i = blockIdx.x * 1024 + threadIdx.x;
    if (i < NN) g_deg[i] = 0;
}

__global__ void hist_kernel(const int* __restrict__ ei) {
    int e = blockIdx.x * blockDim.x + threadIdx.x;
    if (e < EE) atomicAdd(&g_deg[ei[EE + e]], 1);
}

__global__ void scan1_kernel() {
    __shared__ int sh[1024];
    int t = threadIdx.x;
    int idx = blockIdx.x * 1024 + t;
    int v = (idx < NN) ? g_deg[idx] : 0;
    sh[t] = v;
    __syncthreads();
    for (int off = 1; off < 1024; off <<= 1) {
        int u = (t >= off) ? sh[t - off] : 0;
        __syncthreads();
        sh[t] += u;
        __syncthreads();
    }
    if (idx < NN) g_rowptr[idx] = sh[t] - v;
    if (t == 1023) g_bsum[blockIdx.x] = sh[1023];
}

// scan of block sums folded in (each block redundantly scans the 49 sums)
__global__ void scan3_kernel() {
    __shared__ int sh[SCANB];
    int t = threadIdx.x;
    if (t < SCANB) sh[t] = g_bsum[t];
    __syncthreads();
    if (t == 0) {
        int run = 0;
        for (int i = 0; i < SCANB; i++) { int v = sh[i]; sh[i] = run; run += v; }
    }
    __syncthreads();
    int idx = blockIdx.x * 1024 + t;
    if (idx < NN) {
        int r = g_rowptr[idx] + sh[blockIdx.x];
        g_rowptr[idx] = r;
        g_wp[idx] = r;
        if (idx == NN - 1) g_rowptr[NN] = r + g_deg[idx];
    }
}

__global__ void scatter_kernel(const int* __restrict__ ei) {
    int e = blockIdx.x * blockDim.x + threadIdx.x;
    if (e < EE) {
        int d = ei[EE + e];
        int p = atomicAdd(&g_wp[d], 1);
        g_csr[p] = ei[e];
    }
}

// ------- fp16 tensor-core GEMM (m16n8k16, fp32 accum) + fused logits ---------
template <int BM, int BN, int BK, int WM, int WN, int H, bool AF32>
__global__ __launch_bounds__(256) void hgemm_kernel(
        const void* __restrict__ Aptr, const __half* __restrict__ Bh,
        __half* __restrict__ C, int M, int K, int Nn,
        const float* __restrict__ a_s, const float* __restrict__ a_d,
        float* __restrict__ gas, float* __restrict__ gad) {
    constexpr int PAD = 8;
    constexpr int K2 = BK / 2;
    __shared__ uint32_t As2[2][K2][BM + PAD];
    __shared__ uint32_t Bs2[2][K2][BN + PAD];
    constexpr int WARPS_N = BN / WN;
    constexpr int MT = WM / 16, NT = WN / 8;
    constexpr int CB = (BK / 2) * (BN / 8);

    const int tid = threadIdx.x, lane = tid & 31;
    const int wid = tid >> 5;
    const int wm = (wid / WARPS_N) * WM, wn = (wid % WARPS_N) * WN;
    const int bm = blockIdx.x * BM, bn = blockIdx.y * BN;

    float acc[MT][NT][4] = {};

    float4 raf[AF32 ? 4 : 1];
    uint4  rah[AF32 ? 1 : 2];
    uint4 rbl, rbh;
    const int bk2 = tid / (BN / 8), bc8 = tid % (BN / 8);
    const bool bvalid = tid < CB;

    auto load = [&](int k0) {
        if constexpr (AF32) {
            const float* A = (const float*)Aptr;
#pragma unroll
            for (int i = 0; i < 4; i++) {
                int idx = i * 256 + tid;
                int r = idx >> 3, c4 = idx & 7;
                int gr = bm + r;
                raf[i] = (gr < M) ? *reinterpret_cast<const float4*>(&A[gr * K + k0 + 4 * c4])
                                  : make_float4(0.f, 0.f, 0.f, 0.f);
            }
        } else {
            const __half* A = (const __half*)Aptr;
#pragma unroll
            for (int i = 0; i < 2; i++) {
                int idx = i * 256 + tid;
                int r = idx >> 2, c8 = idx & 3;
                int gr = bm + r;
                rah[i] = (gr < M) ? *reinterpret_cast<const uint4*>(&A[(size_t)gr * K + k0 + 8 * c8])
                                  : make_uint4(0u, 0u, 0u, 0u);
            }
        }
        if (bvalid) {
            rbl = *reinterpret_cast<const uint4*>(&Bh[(size_t)(k0 + 2 * bk2) * Nn + bn + 8 * bc8]);
            rbh = *reinterpret_cast<const uint4*>(&Bh[(size_t)(k0 + 2 * bk2 + 1) * Nn + bn + 8 * bc8]);
        }
    };
    auto store = [&](int buf) {
        if constexpr (AF32) {
#pragma unroll
            for (int i = 0; i < 4; i++) {
                int idx = i * 256 + tid;
                int r = idx >> 3, c4 = idx & 7;
                As2[buf][2 * c4][r]     = h2bits(__floats2half2_rn(raf[i].x, raf[i].y));
                As2[buf][2 * c4 + 1][r] = h2bits(__floats2half2_rn(raf[i].z, raf[i].w));
            }
        } else {
#pragma unroll
            for (int i = 0; i < 2; i++) {
                int idx = i * 256 + tid;
                int r = idx >> 2, c8 = idx & 3;
                const uint32_t* p = reinterpret_cast<const uint32_t*>(&rah[i]);
#pragma unroll
                for (int j = 0; j < 4; j++) As2[buf][4 * c8 + j][r] = p[j];
            }
        }
        if (bvalid) {
            const __half* lo = reinterpret_cast<const __half*>(&rbl);
            const __half* hi = reinterpret_cast<const __half*>(&rbh);
            uint32_t tmp[8];
#pragma unroll
            for (int j = 0; j < 8; j++) tmp[j] = h2bits(__halves2half2(lo[j], hi[j]));
            *reinterpret_cast<uint4*>(&Bs2[buf][bk2][8 * bc8])     = *reinterpret_cast<uint4*>(&tmp[0]);
            *reinterpret_cast<uint4*>(&Bs2[buf][bk2][8 * bc8 + 4]) = *reinterpret_cast<uint4*>(&tmp[4]);
        }
    };

    const int ntiles = K / BK;
    load(0);
    store(0);
    __syncthreads();
    int buf = 0;
    const int t4 = lane & 3, g8 = lane >> 2;
    for (int t = 0; t < ntiles; t++) {
        if (t + 1 < ntiles) load((t + 1) * BK);
#pragma unroll
        for (int ks = 0; ks < BK / 16; ks++) {
            const int base = ks * 8;
            uint32_t af[MT][4], bf[NT][2];
#pragma unroll
            for (int mt = 0; mt < MT; mt++) {
                int m0 = wm + mt * 16 + g8;
                af[mt][0] = As2[buf][base + t4][m0];
                af[mt][1] = As2[buf][base + t4][m0 + 8];
                af[mt][2] = As2[buf][base + t4 + 4][m0];
                af[mt][3] = As2[buf][base + t4 + 4][m0 + 8];
            }
#pragma unroll
            for (int nt = 0; nt < NT; nt++) {
                int n0 = wn + nt * 8 + g8;
                bf[nt][0] = Bs2[buf][base + t4][n0];
                bf[nt][1] = Bs2[buf][base + t4 + 4][n0];
            }
#pragma unroll
            for (int mt = 0; mt < MT; mt++)
#pragma unroll
                for (int nt = 0; nt < NT; nt++)
                    asm volatile(
                        "mma.sync.aligned.m16n8k16.row.col.f32.f16.f16.f32 "
                        "{%0,%1,%2,%3},{%4,%5,%6,%7},{%8,%9},{%0,%1,%2,%3};"
                        : "+f"(acc[mt][nt][0]), "+f"(acc[mt][nt][1]),
                          "+f"(acc[mt][nt][2]), "+f"(acc[mt][nt][3])
                        : "r"(af[mt][0]), "r"(af[mt][1]), "r"(af[mt][2]), "r"(af[mt][3]),
                          "r"(bf[nt][0]), "r"(bf[nt][1]));
        }
        if (t + 1 < ntiles) {
            store(buf ^ 1);
            __syncthreads();
            buf ^= 1;
        }
    }

    float asr[NT][2], adr[NT][2];
#pragma unroll
    for (int nt = 0; nt < NT; nt++) {
#pragma unroll
        for (int j = 0; j < 2; j++) {
            int c = bn + wn + nt * 8 + 2 * t4 + j;
            asr[nt][j] = a_s[c];
            adr[nt][j] = a_d[c];
        }
    }
    const int head = (H == 1) ? 0 : ((bn + wn) >> 6);

#pragma unroll
    for (int mt = 0; mt < MT; mt++) {
#pragma unroll
        for (int half_ = 0; half_ < 2; half_++) {
            int row = bm + wm + mt * 16 + g8 + half_ * 8;
            float ps = 0.f, pd = 0.f;
            if (row < M) {
#pragma unroll
                for (int nt = 0; nt < NT; nt++) {
                    int c0 = bn + wn + nt * 8 + 2 * t4;
                    float v0 = acc[mt][nt][half_ * 2 + 0];
                    float v1 = acc[mt][nt][half_ * 2 + 1];
                    *reinterpret_cast<__half2*>(&C[(size_t)row * Nn + c0]) = __floats2half2_rn(v0, v1);
                    ps = fmaf(v0, asr[nt][0], ps); ps = fmaf(v1, asr[nt][1], ps);
                    pd = fmaf(v0, adr[nt][0], pd); pd = fmaf(v1, adr[nt][1], pd);
                }
            }
            ps += __shfl_xor_sync(0xffffffffu, ps, 1);
            ps += __shfl_xor_sync(0xffffffffu, ps, 2);
            pd += __shfl_xor_sync(0xffffffffu, pd, 1);
            pd += __shfl_xor_sync(0xffffffffu, pd, 2);
            if (t4 == 0 && row < M) {
                atomicAdd(&gas[row * H + head], ps);
                atomicAdd(&gad[row * H + head], pd);
            }
        }
    }
}

// -------- single-pass gather aggregation, H=4, fp16 gather, fp16 out ---------
__global__ void agg4_kernel(const __half* __restrict__ h, const float* __restrict__ bias,
                            __half* __restrict__ out,
                            const float* __restrict__ gas, const float* __restrict__ gad) {
    __shared__ float w_sh[8][32 * HEADS];
    __shared__ int   s_sh[8][32];
    const int wid = threadIdx.x >> 5, lane = threadIdx.x & 31;
    const int n = (blockIdx.x * blockDim.x + threadIdx.x) >> 5;
    if (n >= NN) return;

    const int start = g_rowptr[n], end = g_rowptr[n + 1];
    const float4 adv = *reinterpret_cast<const float4*>(&gad[n * 4]);
    const float4 asv = *reinterpret_cast<const float4*>(&gas[n * 4]);
    const float ad[4] = {adv.x, adv.y, adv.z, adv.w};

    float wself[4];
    wself[0] = __expf(leaky(asv.x + ad[0]));
    wself[1] = __expf(leaky(asv.y + ad[1]));
    wself[2] = __expf(leaky(asv.z + ad[2]));
    wself[3] = __expf(leaky(asv.w + ad[3]));

    const int hh = lane >> 3;
    float acc[8];
    {
        uint4 raw = *reinterpret_cast<const uint4*>(&h[(size_t)n * HC + 8 * lane]);
        const __half2* hp = reinterpret_cast<const __half2*>(&raw);
        float w = wself[hh];
#pragma unroll
        for (int j = 0; j < 4; j++) {
            float2 f = __half22float2(hp[j]);
            acc[2 * j]     = f.x * w;
            acc[2 * j + 1] = f.y * w;
        }
    }
    float den[4];
#pragma unroll
    for (int q = 0; q < 4; q++) den[q] = (lane == 0) ? wself[q] : 0.f;

    for (int base = start; base < end; base += 32) {
        int i = base + lane;
        if (i < end) {
            int s = g_csr[i];
            s_sh[wid][lane] = s;
            float4 sa = *reinterpret_cast<const float4*>(&gas[s * 4]);
            float w0 = __expf(leaky(sa.x + ad[0]));
            float w1 = __expf(leaky(sa.y + ad[1]));
            float w2 = __expf(leaky(sa.z + ad[2]));
            float w3 = __expf(leaky(sa.w + ad[3]));
            w_sh[wid][lane * 4 + 0] = w0;
            w_sh[wid][lane * 4 + 1] = w1;
            w_sh[wid][lane * 4 + 2] = w2;
            w_sh[wid][lane * 4 + 3] = w3;
            den[0] += w0; den[1] += w1; den[2] += w2; den[3] += w3;
        }
        __syncwarp();
        int cnt = min(32, end - base);
        for (int k = 0; k < cnt; k++) {
            int s = s_sh[wid][k];
            float w = w_sh[wid][k * 4 + hh];
            uint4 raw = *reinterpret_cast<const uint4*>(&h[(size_t)s * HC + 8 * lane]);
            const __half2* hp = reinterpret_cast<const __half2*>(&raw);
#pragma unroll
            for (int j = 0; j < 4; j++) {
                float2 f = __half22float2(hp[j]);
                acc[2 * j]     = fmaf(f.x, w, acc[2 * j]);
                acc[2 * j + 1] = fmaf(f.y, w, acc[2 * j + 1]);
            }
        }
        __syncwarp();
    }
#pragma unroll
    for (int q = 0; q < 4; q++)
        for (int o = 16; o > 0; o >>= 1)
            den[q] += __shfl_xor_sync(0xffffffffu, den[q], o);
    const float inv = 1.f / (den[hh] + 1e-16f);

    float4 b0 = *reinterpret_cast<const float4*>(&bias[8 * lane]);
    float4 b1 = *reinterpret_cast<const float4*>(&bias[8 * lane + 4]);
    float o0[8];
    o0[0] = fmaf(acc[0], inv, b0.x); o0[1] = fmaf(acc[1], inv, b0.y);
    o0[2] = fmaf(acc[2], inv, b0.z); o0[3] = fmaf(acc[3], inv, b0.w);
    o0[4] = fmaf(acc[4], inv, b1.x); o0[5] = fmaf(acc[5], inv, b1.y);
    o0[6] = fmaf(acc[6], inv, b1.z); o0[7] = fmaf(acc[7], inv, b1.w);
#pragma unroll
    for (int j = 0; j < 8; j++) o0[j] = o0[j] > 0.f ? o0[j] : (__expf(o0[j]) - 1.f);
    uint4 ov;
    __half2* op = reinterpret_cast<__half2*>(&ov);
    op[0] = __floats2half2_rn(o0[0], o0[1]);
    op[1] = __floats2half2_rn(o0[2], o0[3]);
    op[2] = __floats2half2_rn(o0[4], o0[5]);
    op[3] = __floats2half2_rn(o0[6], o0[7]);
    *reinterpret_cast<uint4*>(&out[(size_t)n * HC + 8 * lane]) = ov;
}

// ---- single-pass aggregation, H=1 C=64, fp16 gather, fused mean-pool --------
__global__ void agg1_kernel(const __half* __restrict__ h, const float* __restrict__ bias,
                            const int* __restrict__ batch,
                            const float* __restrict__ gas, const float* __restrict__ gad) {
    __shared__ float w_sh[8][32];
    __shared__ int   s_sh[8][32];
    const int wid = threadIdx.x >> 5, lane = threadIdx.x & 31;
    const int n = (blockIdx.x * blockDim.x + threadIdx.x) >> 5;
    if (n >= NN) return;

    const int start = g_rowptr[n], end = g_rowptr[n + 1];
    const float adv = gad[n];
    const float wself = __expf(leaky(gas[n] + adv));

    float2 acc;
    {
        float2 v = __half22float2(*reinterpret_cast<const __half2*>(&h[(size_t)n * HIDC + 2 * lane]));
        acc = make_float2(v.x * wself, v.y * wself);
    }
    float den = (lane == 0) ? wself : 0.f;

    for (int base = start; base < end; base += 32) {
        int i = base + lane;
        if (i < end) {
            int s = g_csr[i];
            s_sh[wid][lane] = s;
            float w = __expf(leaky(gas[s] + adv));
            w_sh[wid][lane] = w;
            den += w;
        }
        __syncwarp();
        int cnt = min(32, end - base);
        for (int k = 0; k < cnt; k++) {
            int s = s_sh[wid][k];
            float w = w_sh[wid][k];
            float2 v = __half22float2(*reinterpret_cast<const __half2*>(&h[(size_t)s * HIDC + 2 * lane]));
            acc.x = fmaf(v.x, w, acc.x);
            acc.y = fmaf(v.y, w, acc.y);
        }
        __syncwarp();
    }
    for (int o = 16; o > 0; o >>= 1)
        den += __shfl_xor_sync(0xffffffffu, den, o);
    float inv = 1.f / (den + 1e-16f);

    float2 b = *reinterpret_cast<const float2*>(&bias[2 * lane]);
    float vx = fmaf(acc.x, inv, b.x);
    float vy = fmaf(acc.y, inv, b.y);
    vx = vx > 0.f ? vx : (__expf(vx) - 1.f);
    vy = vy > 0.f ? vy : (__expf(vy) - 1.f);

    const int g = batch[n];
    atomicAdd(&g_pool[g * HIDC + 2 * lane], vx);
    atomicAdd(&g_pool[g * HIDC + 2 * lane + 1], vy);
    if (lane == 0) atomicAdd(&g_cnt[g], 1.f);
}

// ---------------- classifier --------------------------------------------------
__global__ void cls_kernel(const float* __restrict__ Wc, const float* __restrict__ bc,
                           float* __restrict__ out) {
    __shared__ float p[HIDC];
    int g = blockIdx.x;
    if (threadIdx.x < HIDC)
        p[threadIdx.x] = g_pool[g * HIDC + threadIdx.x] / fmaxf(g_cnt[g], 1.f);
    __syncthreads();
    for (int k = threadIdx.x; k < NCLS; k += blockDim.x) {
        float s = bc[k];
#pragma unroll
        for (int c = 0; c < HIDC; c++) s += p[c] * Wc[c * NCLS + k];
        out[g * NCLS + k] = s;
    }
}

// ---------------- launch ------------------------------------------------------
extern "C" void kernel_launch(void* const* d_in, const int* in_sizes, int n_in,
                              void* d_out, int out_size) {
    const float* x    = (const float*)d_in[0];
    const int*   ei   = (const int*)d_in[1];
    const int*   batch= (const int*)d_in[2];
    const float* W0   = (const float*)d_in[3];
    const float* as0  = (const float*)d_in[4];
    const float* ad0  = (const float*)d_in[5];
    const float* b0   = (const float*)d_in[6];
    const float* W1   = (const float*)d_in[7];
    const float* as1  = (const float*)d_in[8];
    const float* ad1  = (const float*)d_in[9];
    const float* b1   = (const float*)d_in[10];
    const float* W2   = (const float*)d_in[11];
    const float* as2  = (const float*)d_in[12];
    const float* ad2  = (const float*)d_in[13];
    const float* b2   = (const float*)d_in[14];
    const float* Wc   = (const float*)d_in[15];
    const float* bc   = (const float*)d_in[16];
    float* out = (float*)d_out;

    __half *pH, *pG, *pw0, *pw1, *pw2;
    cudaGetSymbolAddress((void**)&pH, g_bufH);
    cudaGetSymbolAddress((void**)&pG, g_bufG);
    cudaGetSymbolAddress((void**)&pw0, g_w0h);
    cudaGetSymbolAddress((void**)&pw1, g_w1h);
    cudaGetSymbolAddress((void**)&pw2, g_w2h);
    float *pas0, *pad0, *pas1, *pad1, *pas2, *pad2;
    cudaGetSymbolAddress((void**)&pas0, g_as0);
    cudaGetSymbolAddress((void**)&pad0, g_ad0);
    cudaGetSymbolAddress((void**)&pas1, g_as1);
    cudaGetSymbolAddress((void**)&pad1, g_ad1);
    cudaGetSymbolAddress((void**)&pas2, g_as2);
    cudaGetSymbolAddress((void**)&pad2, g_ad2);

    // ---- fork: CSR build on side stream, weights/zero + GEMM0 on main -------
    // Stream/events are created exactly once (first call) and reused on every
    // subsequent call (including the capture call) — identical, deterministic
    // launch sequence each time; no capture-state queries, no destruction.
    static cudaStream_t s2 = nullptr;
    static cudaEvent_t evF = nullptr, evJ = nullptr;
    if (s2 == nullptr) {
        cudaStreamCreateWithFlags(&s2, cudaStreamNonBlocking);
        cudaEventCreateWithFlags(&evF, cudaEventDisableTiming);
        cudaEventCreateWithFlags(&evJ, cudaEventDisableTiming);
    }

    cudaEventRecord(evF, 0);
    cudaStreamWaitEvent(s2, evF, 0);

    zdeg_kernel<<<SCANB, 1024, 0, s2>>>();
    hist_kernel<<<(EE + 255) / 256, 256, 0, s2>>>(ei);
    scan1_kernel<<<SCANB, 1024, 0, s2>>>();
    scan3_kernel<<<SCANB, 1024, 0, s2>>>();
    scatter_kernel<<<(EE + 255) / 256, 256, 0, s2>>>(ei);
    cudaEventRecord(evJ, s2);

    prep0_kernel<<<196, 256>>>(W0, W1, W2);

    const int wgrid = (NN * 32 + 255) / 256;

    // layer 0: [50000,128] @ [128,256]  (A fp32)
    dim3 g0((NN + 127) / 128, HC / 128);
    hgemm_kernel<128, 128, 32, 64, 32, HEADS, true><<<g0, 256>>>(
        x, pw0, pH, NN, INC, HC, as0, ad0, pas0, pad0);

    // join CSR before first aggregation
    cudaStreamWaitEvent(0, evJ, 0);
    agg4_kernel<<<wgrid, 256>>>(pH, b0, pG, pas0, pad0);

    // layer 1: [50000,256] @ [256,256]  (A fp16)
    hgemm_kernel<128, 128, 32, 64, 32, HEADS, false><<<g0, 256>>>(
        pG, pw1, pH, NN, HC, HC, as1, ad1, pas1, pad1);
    agg4_kernel<<<wgrid, 256>>>(pH, b1, pG, pas1, pad1);

    // layer 2: [50000,256] @ [256,64] (single head), fused pool
    dim3 g2((NN + 127) / 128, 1);
    hgemm_kernel<128, 64, 32, 32, 32, 1, false><<<g2, 256>>>(
        pG, pw2, pH, NN, HC, HIDC, as2, ad2, pas2, pad2);
    agg1_kernel<<<wgrid, 256>>>(pH, b2, batch, pas2, pad2);

    cls_kernel<<<GG, 256>>>(Wc, bc, out);
}